// round 5
// baseline (speedup 1.0000x reference)
#include <cuda_runtime.h>
#include <cuda_bf16.h>

#define B_ 4
#define T_ 2048
#define C_ 1024
#define H_ 16
#define HD_ 64

// ---------------- scratch (allocation-free: __device__ globals) ----------------
__device__ float g_q[B_*H_*T_*HD_];   // 32 MB  [B,H,T,HD]
__device__ float g_k[B_*H_*T_*HD_];   // 32 MB
__device__ float g_v[B_*H_*T_*HD_];   // 32 MB
__device__ float g_y[B_*T_*C_];       // 32 MB  [B,T,C]
__device__ float g_wt[4*C_*C_];       // 16 MB  transposed weights

// ---------------- weight transpose: Wt[k][n] = W[n][k] ----------------
__global__ void transpose_k(const float* __restrict__ in, float* __restrict__ out) {
    __shared__ float tile[32][33];
    int x = blockIdx.x * 32 + threadIdx.x;
    int y = blockIdx.y * 32 + threadIdx.y;
#pragma unroll
    for (int r = 0; r < 32; r += 8)
        tile[threadIdx.y + r][threadIdx.x] = in[(size_t)(y + r) * C_ + x];
    __syncthreads();
    int x2 = blockIdx.y * 32 + threadIdx.x;
    int y2 = blockIdx.x * 32 + threadIdx.y;
#pragma unroll
    for (int r = 0; r < 32; r += 8)
        out[(size_t)(y2 + r) * C_ + x2] = tile[threadIdx.x][threadIdx.y + r];
}

// ---------------- SGEMM: out = A[M,1024] @ Wt[1024,1024] + bias ----------------
// headed=1: col n -> head h=n/64, d=n%64; row m -> b=m/T, t=m%T; write [B,H,T,HD]
// headed=0: plain row-major [M,1024]
__global__ __launch_bounds__(256) void sgemm_bias(
    const float* __restrict__ A, const float* __restrict__ Wt,
    const float* __restrict__ bias, float* __restrict__ out, int headed)
{
    const int K = 1024, N = 1024;
    __shared__ float As[8][128];
    __shared__ float Bs[8][128];
    int tid = threadIdx.x;
    int m0 = blockIdx.y * 128;
    int n0 = blockIdx.x * 128;
    int tx = tid & 15, ty = tid >> 4;

    int arow = tid >> 1, acol = (tid & 1) * 4;   // A tile 128x8
    int brow = tid >> 5, bcol = (tid & 31) * 4;  // B tile 8x128
    const float* Ap = A + (size_t)(m0 + arow) * K + acol;
    const float* Bp = Wt + (size_t)brow * N + n0 + bcol;

    float acc[8][8] = {};

    for (int k0 = 0; k0 < K; k0 += 8) {
        float4 av = *(const float4*)(Ap + k0);
        As[acol + 0][arow] = av.x;
        As[acol + 1][arow] = av.y;
        As[acol + 2][arow] = av.z;
        As[acol + 3][arow] = av.w;
        *(float4*)&Bs[brow][bcol] = *(const float4*)(Bp + (size_t)k0 * N);
        __syncthreads();
#pragma unroll
        for (int kk = 0; kk < 8; kk++) {
            float4 a0 = *(const float4*)&As[kk][ty * 8];
            float4 a1 = *(const float4*)&As[kk][ty * 8 + 4];
            float4 b0 = *(const float4*)&Bs[kk][tx * 8];
            float4 b1 = *(const float4*)&Bs[kk][tx * 8 + 4];
            float ra[8] = {a0.x, a0.y, a0.z, a0.w, a1.x, a1.y, a1.z, a1.w};
            float rb[8] = {b0.x, b0.y, b0.z, b0.w, b1.x, b1.y, b1.z, b1.w};
#pragma unroll
            for (int i = 0; i < 8; i++)
#pragma unroll
                for (int j = 0; j < 8; j++)
                    acc[i][j] += ra[i] * rb[j];
        }
        __syncthreads();
    }

#pragma unroll
    for (int i = 0; i < 8; i++) {
        int m = m0 + ty * 8 + i;
#pragma unroll
        for (int j4 = 0; j4 < 8; j4 += 4) {
            int n = n0 + tx * 8 + j4;
            float4 o;
            o.x = acc[i][j4 + 0] + bias[n + 0];
            o.y = acc[i][j4 + 1] + bias[n + 1];
            o.z = acc[i][j4 + 2] + bias[n + 2];
            o.w = acc[i][j4 + 3] + bias[n + 3];
            if (headed) {
                int b = m >> 11, t = m & 2047;
                int h = n >> 6,  d = n & 63;
                *(float4*)&out[((size_t)((b << 4) + h) * T_ + t) * HD_ + d] = o;
            } else {
                *(float4*)&out[(size_t)m * N + n] = o;
            }
        }
    }
}

// ---------------- flash attention with RL mask ----------------
// mask: allowed iff (col <= row) && (col % 25 != 24)
// Block: 64 query rows for one (b,h). 256 threads, 16x16; each thread owns a
// 4x4 S micro-tile (rows ty*4.., cols tx*4..) and 4x4 of O (rows ty*4.., d tx*4..).
// Smem padding stride must be a multiple of 4 floats so LDS.128 stays 16B-aligned.
#define PAD_ 68
__global__ __launch_bounds__(256) void attn_kernel(
    const float* __restrict__ q, const float* __restrict__ k,
    const float* __restrict__ v, float* __restrict__ y)
{
    extern __shared__ float sm[];
    float* qs = sm;                  // [64][PAD_] d-major: qs[d*PAD_+m]
    float* ks = qs + 64 * PAD_;      // [64][PAD_] d-major: ks[d*PAD_+n]
    float* ps = ks + 64 * PAD_;      // [64][PAD_] n-major: ps[n*PAD_+m]
    float* vs = ps + 64 * PAD_;      // [64][64]   n-major: vs[n*64+d]

    int tid = threadIdx.x;
    int tx = tid & 15, ty = tid >> 4;
    int qi = blockIdx.x, h = blockIdx.y, b = blockIdx.z;
    int i0 = qi * 64;

    const float* qb = q + ((size_t)(b * H_ + h) * T_ + i0) * HD_;
    const float* kb = k + (size_t)(b * H_ + h) * T_ * HD_;
    const float* vb = v + (size_t)(b * H_ + h) * T_ * HD_;

    // load Q tile, transposed into [d][m]
#pragma unroll
    for (int l = 0; l < 4; l++) {
        int idx = tid + 256 * l;
        int m = idx >> 4, d4 = (idx & 15) << 2;
        float4 t4 = *(const float4*)(qb + m * 64 + d4);
        qs[(d4 + 0) * PAD_ + m] = t4.x;
        qs[(d4 + 1) * PAD_ + m] = t4.y;
        qs[(d4 + 2) * PAD_ + m] = t4.z;
        qs[(d4 + 3) * PAD_ + m] = t4.w;
    }

    float acc[4][4] = {};
    float Mr[4], Lr[4];
#pragma unroll
    for (int i = 0; i < 4; i++) { Mr[i] = -1e30f; Lr[i] = 0.f; }
    const float scale = 0.125f;  // 1/sqrt(64)
    int rr[4];
#pragma unroll
    for (int i = 0; i < 4; i++) rr[i] = i0 + ty * 4 + i;

    int nt = qi + 1;  // causal: key tiles 0..qi
    for (int t = 0; t < nt; t++) {
        int j0 = t * 64;
        // load K tile transposed [d][n]
#pragma unroll
        for (int l = 0; l < 4; l++) {
            int idx = tid + 256 * l;
            int m = idx >> 4, d4 = (idx & 15) << 2;
            float4 t4 = *(const float4*)(kb + (size_t)(j0 + m) * 64 + d4);
            ks[(d4 + 0) * PAD_ + m] = t4.x;
            ks[(d4 + 1) * PAD_ + m] = t4.y;
            ks[(d4 + 2) * PAD_ + m] = t4.z;
            ks[(d4 + 3) * PAD_ + m] = t4.w;
        }
        // load V tile natural [n][d]
#pragma unroll
        for (int l = 0; l < 4; l++) {
            int idx = tid + 256 * l;
            ((float4*)vs)[idx] = *(const float4*)(vb + (size_t)j0 * 64 + idx * 4);
        }
        __syncthreads();

        // S = Q K^T  (4x4 per thread)
        float s[4][4] = {};
#pragma unroll 16
        for (int d = 0; d < 64; d++) {
            float4 aq = *(const float4*)&qs[d * PAD_ + ty * 4];
            float4 ak = *(const float4*)&ks[d * PAD_ + tx * 4];
            float ra[4] = {aq.x, aq.y, aq.z, aq.w};
            float rb[4] = {ak.x, ak.y, ak.z, ak.w};
#pragma unroll
            for (int i = 0; i < 4; i++)
#pragma unroll
                for (int j = 0; j < 4; j++) s[i][j] += ra[i] * rb[j];
        }

        // mask + streaming softmax
        int cbase = j0 + tx * 4;
        bool cok[4];
#pragma unroll
        for (int j = 0; j < 4; j++) cok[j] = (((cbase + j) % 25) != 24);
#pragma unroll
        for (int i = 0; i < 4; i++) {
            float mx = -1e30f;
#pragma unroll
            for (int j = 0; j < 4; j++) {
                bool ok = cok[j] && (cbase + j <= rr[i]);
                s[i][j] = ok ? s[i][j] * scale : -1e30f;
                mx = fmaxf(mx, s[i][j]);
            }
#pragma unroll
            for (int o = 8; o >= 1; o >>= 1)
                mx = fmaxf(mx, __shfl_xor_sync(0xffffffffu, mx, o, 16));
            float Mn = fmaxf(Mr[i], mx);
            float al = __expf(Mr[i] - Mn);  // exp(0)=1 safe when both -1e30
            Mr[i] = Mn;
            float rs = 0.f;
#pragma unroll
            for (int j = 0; j < 4; j++) {
                float p = (s[i][j] > -1e29f) ? __expf(s[i][j] - Mn) : 0.f;
                s[i][j] = p;
                rs += p;
            }
#pragma unroll
            for (int o = 8; o >= 1; o >>= 1)
                rs += __shfl_xor_sync(0xffffffffu, rs, o, 16);
            Lr[i] = Lr[i] * al + rs;
#pragma unroll
            for (int j = 0; j < 4; j++) acc[i][j] *= al;
        }

        // stage P in shared [n][m]
#pragma unroll
        for (int i = 0; i < 4; i++)
#pragma unroll
            for (int j = 0; j < 4; j++)
                ps[(tx * 4 + j) * PAD_ + ty * 4 + i] = s[i][j];
        __syncthreads();

        // O += P V
#pragma unroll 16
        for (int n = 0; n < 64; n++) {
            float4 pp = *(const float4*)&ps[n * PAD_ + ty * 4];
            float4 vv = *(const float4*)&vs[n * 64 + tx * 4];
            float pr[4] = {pp.x, pp.y, pp.z, pp.w};
            float vr[4] = {vv.x, vv.y, vv.z, vv.w};
#pragma unroll
            for (int i = 0; i < 4; i++)
#pragma unroll
                for (int j = 0; j < 4; j++) acc[i][j] += pr[i] * vr[j];
        }
        __syncthreads();  // protect ks/vs/ps for next tile's loads
    }

    // epilogue: normalize and write [B,T,C] (c = h*64 + d)
#pragma unroll
    for (int i = 0; i < 4; i++) {
        float inv = 1.0f / Lr[i];
        float4 o;
        o.x = acc[i][0] * inv;
        o.y = acc[i][1] * inv;
        o.z = acc[i][2] * inv;
        o.w = acc[i][3] * inv;
        *(float4*)&y[((size_t)(b * T_) + rr[i]) * C_ + h * 64 + tx * 4] = o;
    }
}

// ---------------- launch ----------------
extern "C" void kernel_launch(void* const* d_in, const int* in_sizes, int n_in,
                              void* d_out, int out_size) {
    const float* x  = (const float*)d_in[0];
    const float* Wq = (const float*)d_in[1];
    const float* bq = (const float*)d_in[2];
    const float* Wk = (const float*)d_in[3];
    const float* bk = (const float*)d_in[4];
    const float* Wv = (const float*)d_in[5];
    const float* bv = (const float*)d_in[6];
    const float* Wp = (const float*)d_in[7];
    const float* bp = (const float*)d_in[8];

    float *q, *k, *v, *y, *wt;
    cudaGetSymbolAddress((void**)&q, g_q);
    cudaGetSymbolAddress((void**)&k, g_k);
    cudaGetSymbolAddress((void**)&v, g_v);
    cudaGetSymbolAddress((void**)&y, g_y);
    cudaGetSymbolAddress((void**)&wt, g_wt);
    float* wtq = wt;
    float* wtk = wt + (size_t)C_ * C_;
    float* wtv = wt + 2 * (size_t)C_ * C_;
    float* wtp = wt + 3 * (size_t)C_ * C_;

    dim3 tb(32, 8), tg(32, 32);
    transpose_k<<<tg, tb>>>(Wq, wtq);
    transpose_k<<<tg, tb>>>(Wk, wtk);
    transpose_k<<<tg, tb>>>(Wv, wtv);
    transpose_k<<<tg, tb>>>(Wp, wtp);

    dim3 gg(8, 64);  // N/128, M/128 with M = B*T = 8192
    sgemm_bias<<<gg, 256>>>(x, wtq, bq, q, 1);
    sgemm_bias<<<gg, 256>>>(x, wtk, bk, k, 1);
    sgemm_bias<<<gg, 256>>>(x, wtv, bv, v, 1);

    const int ATT_SMEM = (64 * PAD_ * 3 + 64 * 64) * (int)sizeof(float);  // 68608 B
    cudaFuncSetAttribute(attn_kernel, cudaFuncAttributeMaxDynamicSharedMemorySize, ATT_SMEM);
    attn_kernel<<<dim3(T_ / 64, H_, B_), 256, ATT_SMEM>>>(q, k, v, y);

    sgemm_bias<<<gg, 256>>>(y, wtp, bp, (float*)d_out, 0);
}

// round 8
// speedup vs baseline: 1.4631x; 1.4631x over previous
#include <cuda_runtime.h>
#include <cuda_bf16.h>
#include <cstdint>

#define B_ 4
#define T_ 2048
#define C_ 1024
#define H_ 16
#define HD_ 64

// ---------------- scratch (allocation-free: __device__ globals) ----------------
__device__ float g_q[B_*H_*T_*HD_];   // 32 MB  [B,H,T,HD]
__device__ float g_k[B_*H_*T_*HD_];   // 32 MB
__device__ float g_v[B_*H_*T_*HD_];   // 32 MB
__device__ float g_y[B_*T_*C_];       // 32 MB  [B,T,C]

// ---------------- helpers ----------------
__device__ __forceinline__ uint32_t f2tf32(float x) {
    uint32_t r;
    asm("cvt.rna.tf32.f32 %0, %1;" : "=r"(r) : "f"(x));
    return r;
}

__device__ __forceinline__ void mma_tf32_k8(
    float* c, uint32_t a0, uint32_t a1, uint32_t a2, uint32_t a3,
    uint32_t b0, uint32_t b1)
{
    asm volatile(
        "mma.sync.aligned.m16n8k8.row.col.f32.tf32.tf32.f32 "
        "{%0,%1,%2,%3}, {%4,%5,%6,%7}, {%8,%9}, {%0,%1,%2,%3};"
        : "+f"(c[0]), "+f"(c[1]), "+f"(c[2]), "+f"(c[3])
        : "r"(a0), "r"(a1), "r"(a2), "r"(a3), "r"(b0), "r"(b1));
}

// ---------------- tf32 GEMM: out = A[M,1024] @ W^T + bias ----------------
// A row-major [M,K]; W row-major [N,K] (torch Linear weight) == mma .col B operand.
// headed=1: col n -> (h=n/64, d=n%64), row m -> (b=m/T, t=m%T); write [B,H,T,HD]
// headed=0: plain row-major [M,N]
// Tile 128x128x16, 8 warps (2x4), warp tile 64x32 (4x4 mma grid of m16n8k8).
// Smem k-permuted: element k of a row stored at (k&3)*4 + (k>>2), so one
// LDS.128 at [row*16 + (lane&3)*4] yields k = {q, q+4, q+8, q+12}: both k-steps.
__global__ __launch_bounds__(256) void gemm_tf32(
    const float* __restrict__ A, const float* __restrict__ W,
    const float* __restrict__ bias, float* __restrict__ out, int headed)
{
    const int K = 1024, N = 1024;
    __shared__ uint32_t As[128 * 16];
    __shared__ uint32_t Bs[128 * 16];

    int tid = threadIdx.x;
    int lane = tid & 31, warp = tid >> 5;
    int wm = warp & 1, wn = warp >> 1;     // 2 (M) x 4 (N)
    int m0 = blockIdx.y * 128, n0 = blockIdx.x * 128;
    int r = lane >> 2, q = lane & 3;

    float acc[16][4] = {};                  // [mt*4+nt][c0..c3]

    for (int k0 = 0; k0 < K; k0 += 16) {
        // ---- stage A & B tiles (tf32-converted, k-permuted) ----
#pragma unroll
        for (int l = 0; l < 2; l++) {
            int fi = tid + l * 256;             // 0..511 float4s
            int row = fi >> 2;
            int kq  = (fi & 3) << 2;            // k offset of this float4
            float4 av = *(const float4*)(A + (size_t)(m0 + row) * K + k0 + kq);
            float4 bv = *(const float4*)(W + (size_t)(n0 + row) * K + k0 + kq);
            int base = row * 16 + (kq >> 2);
            As[base + 0]  = f2tf32(av.x);
            As[base + 4]  = f2tf32(av.y);
            As[base + 8]  = f2tf32(av.z);
            As[base + 12] = f2tf32(av.w);
            Bs[base + 0]  = f2tf32(bv.x);
            Bs[base + 4]  = f2tf32(bv.y);
            Bs[base + 8]  = f2tf32(bv.z);
            Bs[base + 12] = f2tf32(bv.w);
        }
        __syncthreads();

        // ---- load fragments ----
        uint4 aLo[4], aHi[4], bV[4];
#pragma unroll
        for (int mt = 0; mt < 4; mt++) {
            int row = wm * 64 + mt * 16 + r;
            aLo[mt] = *(const uint4*)&As[row * 16 + q * 4];
            aHi[mt] = *(const uint4*)&As[(row + 8) * 16 + q * 4];
        }
#pragma unroll
        for (int nt = 0; nt < 4; nt++) {
            int col = wn * 32 + nt * 8 + r;     // n-index for B fragment
            bV[nt] = *(const uint4*)&Bs[col * 16 + q * 4];
        }

        // ---- 32 mma (4 mt x 4 nt x 2 k-steps) ----
#pragma unroll
        for (int mt = 0; mt < 4; mt++)
#pragma unroll
            for (int nt = 0; nt < 4; nt++) {
                float* c = acc[mt * 4 + nt];
                mma_tf32_k8(c, aLo[mt].x, aHi[mt].x, aLo[mt].y, aHi[mt].y,
                            bV[nt].x, bV[nt].y);                 // k 0..7
                mma_tf32_k8(c, aLo[mt].z, aHi[mt].z, aLo[mt].w, aHi[mt].w,
                            bV[nt].z, bV[nt].w);                 // k 8..15
            }
        __syncthreads();
    }

    // ---- epilogue: bias + (optional) head scatter ----
#pragma unroll
    for (int mt = 0; mt < 4; mt++) {
        int rowb = m0 + wm * 64 + mt * 16 + r;
#pragma unroll
        for (int nt = 0; nt < 4; nt++) {
            int colb = n0 + wn * 32 + nt * 8 + q * 2;
            float bb0 = bias[colb], bb1 = bias[colb + 1];
            float* c = acc[mt * 4 + nt];
#pragma unroll
            for (int hh = 0; hh < 2; hh++) {
                int m = rowb + hh * 8;
                float2 o;
                o.x = c[hh * 2 + 0] + bb0;
                o.y = c[hh * 2 + 1] + bb1;
                if (headed) {
                    int b = m >> 11, t = m & 2047;
                    int h = colb >> 6, d = colb & 63;
                    *(float2*)&out[((size_t)((b << 4) + h) * T_ + t) * HD_ + d] = o;
                } else {
                    *(float2*)&out[(size_t)m * N + colb] = o;
                }
            }
        }
    }
}

// ---------------- flash attention with RL mask (unchanged from R4) ----------------
// mask: allowed iff (col <= row) && (col % 25 != 24)
#define PAD_ 68
__global__ __launch_bounds__(256) void attn_kernel(
    const float* __restrict__ q, const float* __restrict__ k,
    const float* __restrict__ v, float* __restrict__ y)
{
    extern __shared__ float sm[];
    float* qs = sm;                  // [64][PAD_] d-major
    float* ks = qs + 64 * PAD_;      // [64][PAD_] d-major
    float* ps = ks + 64 * PAD_;      // [64][PAD_] n-major
    float* vs = ps + 64 * PAD_;      // [64][64]   n-major

    int tid = threadIdx.x;
    int tx = tid & 15, ty = tid >> 4;
    int qi = blockIdx.x, h = blockIdx.y, b = blockIdx.z;
    int i0 = qi * 64;

    const float* qb = q + ((size_t)(b * H_ + h) * T_ + i0) * HD_;
    const float* kb = k + (size_t)(b * H_ + h) * T_ * HD_;
    const float* vb = v + (size_t)(b * H_ + h) * T_ * HD_;

#pragma unroll
    for (int l = 0; l < 4; l++) {
        int idx = tid + 256 * l;
        int m = idx >> 4, d4 = (idx & 15) << 2;
        float4 t4 = *(const float4*)(qb + m * 64 + d4);
        qs[(d4 + 0) * PAD_ + m] = t4.x;
        qs[(d4 + 1) * PAD_ + m] = t4.y;
        qs[(d4 + 2) * PAD_ + m] = t4.z;
        qs[(d4 + 3) * PAD_ + m] = t4.w;
    }

    float acc[4][4] = {};
    float Mr[4], Lr[4];
#pragma unroll
    for (int i = 0; i < 4; i++) { Mr[i] = -1e30f; Lr[i] = 0.f; }
    const float scale = 0.125f;
    int rr[4];
#pragma unroll
    for (int i = 0; i < 4; i++) rr[i] = i0 + ty * 4 + i;

    int nt = qi + 1;
    for (int t = 0; t < nt; t++) {
        int j0 = t * 64;
#pragma unroll
        for (int l = 0; l < 4; l++) {
            int idx = tid + 256 * l;
            int m = idx >> 4, d4 = (idx & 15) << 2;
            float4 t4 = *(const float4*)(kb + (size_t)(j0 + m) * 64 + d4);
            ks[(d4 + 0) * PAD_ + m] = t4.x;
            ks[(d4 + 1) * PAD_ + m] = t4.y;
            ks[(d4 + 2) * PAD_ + m] = t4.z;
            ks[(d4 + 3) * PAD_ + m] = t4.w;
        }
#pragma unroll
        for (int l = 0; l < 4; l++) {
            int idx = tid + 256 * l;
            ((float4*)vs)[idx] = *(const float4*)(vb + (size_t)j0 * 64 + idx * 4);
        }
        __syncthreads();

        float s[4][4] = {};
#pragma unroll 16
        for (int d = 0; d < 64; d++) {
            float4 aq = *(const float4*)&qs[d * PAD_ + ty * 4];
            float4 ak = *(const float4*)&ks[d * PAD_ + tx * 4];
            float ra[4] = {aq.x, aq.y, aq.z, aq.w};
            float rb[4] = {ak.x, ak.y, ak.z, ak.w};
#pragma unroll
            for (int i = 0; i < 4; i++)
#pragma unroll
                for (int j = 0; j < 4; j++) s[i][j] += ra[i] * rb[j];
        }

        int cbase = j0 + tx * 4;
        bool cok[4];
#pragma unroll
        for (int j = 0; j < 4; j++) cok[j] = (((cbase + j) % 25) != 24);
#pragma unroll
        for (int i = 0; i < 4; i++) {
            float mx = -1e30f;
#pragma unroll
            for (int j = 0; j < 4; j++) {
                bool ok = cok[j] && (cbase + j <= rr[i]);
                s[i][j] = ok ? s[i][j] * scale : -1e30f;
                mx = fmaxf(mx, s[i][j]);
            }
#pragma unroll
            for (int o = 8; o >= 1; o >>= 1)
                mx = fmaxf(mx, __shfl_xor_sync(0xffffffffu, mx, o, 16));
            float Mn = fmaxf(Mr[i], mx);
            float al = __expf(Mr[i] - Mn);
            Mr[i] = Mn;
            float rs = 0.f;
#pragma unroll
            for (int j = 0; j < 4; j++) {
                float p = (s[i][j] > -1e29f) ? __expf(s[i][j] - Mn) : 0.f;
                s[i][j] = p;
                rs += p;
            }
#pragma unroll
            for (int o = 8; o >= 1; o >>= 1)
                rs += __shfl_xor_sync(0xffffffffu, rs, o, 16);
            Lr[i] = Lr[i] * al + rs;
#pragma unroll
            for (int j = 0; j < 4; j++) acc[i][j] *= al;
        }

#pragma unroll
        for (int i = 0; i < 4; i++)
#pragma unroll
            for (int j = 0; j < 4; j++)
                ps[(tx * 4 + j) * PAD_ + ty * 4 + i] = s[i][j];
        __syncthreads();

#pragma unroll 16
        for (int n = 0; n < 64; n++) {
            float4 pp = *(const float4*)&ps[n * PAD_ + ty * 4];
            float4 vv = *(const float4*)&vs[n * 64 + tx * 4];
            float pr[4] = {pp.x, pp.y, pp.z, pp.w};
            float vr[4] = {vv.x, vv.y, vv.z, vv.w};
#pragma unroll
            for (int i = 0; i < 4; i++)
#pragma unroll
                for (int j = 0; j < 4; j++) acc[i][j] += pr[i] * vr[j];
        }
        __syncthreads();
    }

#pragma unroll
    for (int i = 0; i < 4; i++) {
        float inv = 1.0f / Lr[i];
        float4 o;
        o.x = acc[i][0] * inv;
        o.y = acc[i][1] * inv;
        o.z = acc[i][2] * inv;
        o.w = acc[i][3] * inv;
        *(float4*)&y[((size_t)(b * T_) + rr[i]) * C_ + h * 64 + tx * 4] = o;
    }
}

// ---------------- launch ----------------
extern "C" void kernel_launch(void* const* d_in, const int* in_sizes, int n_in,
                              void* d_out, int out_size) {
    const float* x  = (const float*)d_in[0];
    const float* Wq = (const float*)d_in[1];
    const float* bq = (const float*)d_in[2];
    const float* Wk = (const float*)d_in[3];
    const float* bk = (const float*)d_in[4];
    const float* Wv = (const float*)d_in[5];
    const float* bv = (const float*)d_in[6];
    const float* Wp = (const float*)d_in[7];
    const float* bp = (const float*)d_in[8];

    float *q, *k, *v, *y;
    cudaGetSymbolAddress((void**)&q, g_q);
    cudaGetSymbolAddress((void**)&k, g_k);
    cudaGetSymbolAddress((void**)&v, g_v);
    cudaGetSymbolAddress((void**)&y, g_y);

    dim3 gg(8, 64);  // N/128, M/128 with M = B*T = 8192
    gemm_tf32<<<gg, 256>>>(x, Wq, bq, q, 1);
    gemm_tf32<<<gg, 256>>>(x, Wk, bk, k, 1);
    gemm_tf32<<<gg, 256>>>(x, Wv, bv, v, 1);

    const int ATT_SMEM = (64 * PAD_ * 3 + 64 * 64) * (int)sizeof(float);  // 68608 B
    cudaFuncSetAttribute(attn_kernel, cudaFuncAttributeMaxDynamicSharedMemorySize, ATT_SMEM);
    attn_kernel<<<dim3(T_ / 64, H_, B_), 256, ATT_SMEM>>>(q, k, v, y);

    gemm_tf32<<<gg, 256>>>(y, Wp, bp, (float*)d_out, 0);
}

// round 11
// speedup vs baseline: 2.0813x; 1.4226x over previous
#include <cuda_runtime.h>
#include <cuda_bf16.h>
#include <cstdint>

#define B_ 4
#define T_ 2048
#define C_ 1024
#define H_ 16
#define HD_ 64

// ---------------- scratch (allocation-free: __device__ globals) ----------------
__device__ float g_q[B_*H_*T_*HD_];   // 32 MB  [B,H,T,HD]
__device__ float g_k[B_*H_*T_*HD_];   // 32 MB
__device__ float g_v[B_*H_*T_*HD_];   // 32 MB
__device__ float g_y[B_*T_*C_];       // 32 MB  [B,T,C]

// ---------------- helpers ----------------
__device__ __forceinline__ uint32_t f2tf32(float x) {
    uint32_t r;
    asm("cvt.rna.tf32.f32 %0, %1;" : "=r"(r) : "f"(x));
    return r;
}

__device__ __forceinline__ void mma_tf32_k8(
    float* c, uint32_t a0, uint32_t a1, uint32_t a2, uint32_t a3,
    uint32_t b0, uint32_t b1)
{
    asm volatile(
        "mma.sync.aligned.m16n8k8.row.col.f32.tf32.tf32.f32 "
        "{%0,%1,%2,%3}, {%4,%5,%6,%7}, {%8,%9}, {%0,%1,%2,%3};"
        : "+f"(c[0]), "+f"(c[1]), "+f"(c[2]), "+f"(c[3])
        : "r"(a0), "r"(a1), "r"(a2), "r"(a3), "r"(b0), "r"(b1));
}

// ---------------- tf32 GEMM: out = A[M,1024] @ W^T + bias (unchanged, proven) ----
__global__ __launch_bounds__(256) void gemm_tf32(
    const float* __restrict__ A, const float* __restrict__ W,
    const float* __restrict__ bias, float* __restrict__ out, int headed)
{
    const int K = 1024, N = 1024;
    __shared__ uint32_t As[128 * 16];
    __shared__ uint32_t Bs[128 * 16];

    int tid = threadIdx.x;
    int lane = tid & 31, warp = tid >> 5;
    int wm = warp & 1, wn = warp >> 1;     // 2 (M) x 4 (N)
    int m0 = blockIdx.y * 128, n0 = blockIdx.x * 128;
    int r = lane >> 2, q = lane & 3;

    float acc[16][4] = {};

    for (int k0 = 0; k0 < K; k0 += 16) {
#pragma unroll
        for (int l = 0; l < 2; l++) {
            int fi = tid + l * 256;
            int row = fi >> 2;
            int kq  = (fi & 3) << 2;
            float4 av = *(const float4*)(A + (size_t)(m0 + row) * K + k0 + kq);
            float4 bv = *(const float4*)(W + (size_t)(n0 + row) * K + k0 + kq);
            int base = row * 16 + (kq >> 2);
            As[base + 0]  = f2tf32(av.x);
            As[base + 4]  = f2tf32(av.y);
            As[base + 8]  = f2tf32(av.z);
            As[base + 12] = f2tf32(av.w);
            Bs[base + 0]  = f2tf32(bv.x);
            Bs[base + 4]  = f2tf32(bv.y);
            Bs[base + 8]  = f2tf32(bv.z);
            Bs[base + 12] = f2tf32(bv.w);
        }
        __syncthreads();

        uint4 aLo[4], aHi[4], bV[4];
#pragma unroll
        for (int mt = 0; mt < 4; mt++) {
            int row = wm * 64 + mt * 16 + r;
            aLo[mt] = *(const uint4*)&As[row * 16 + q * 4];
            aHi[mt] = *(const uint4*)&As[(row + 8) * 16 + q * 4];
        }
#pragma unroll
        for (int nt = 0; nt < 4; nt++) {
            int col = wn * 32 + nt * 8 + r;
            bV[nt] = *(const uint4*)&Bs[col * 16 + q * 4];
        }

#pragma unroll
        for (int mt = 0; mt < 4; mt++)
#pragma unroll
            for (int nt = 0; nt < 4; nt++) {
                float* c = acc[mt * 4 + nt];
                mma_tf32_k8(c, aLo[mt].x, aHi[mt].x, aLo[mt].y, aHi[mt].y,
                            bV[nt].x, bV[nt].y);
                mma_tf32_k8(c, aLo[mt].z, aHi[mt].z, aLo[mt].w, aHi[mt].w,
                            bV[nt].z, bV[nt].w);
            }
        __syncthreads();
    }

#pragma unroll
    for (int mt = 0; mt < 4; mt++) {
        int rowb = m0 + wm * 64 + mt * 16 + r;
#pragma unroll
        for (int nt = 0; nt < 4; nt++) {
            int colb = n0 + wn * 32 + nt * 8 + q * 2;
            float bb0 = bias[colb], bb1 = bias[colb + 1];
            float* c = acc[mt * 4 + nt];
#pragma unroll
            for (int hh = 0; hh < 2; hh++) {
                int m = rowb + hh * 8;
                float2 o;
                o.x = c[hh * 2 + 0] + bb0;
                o.y = c[hh * 2 + 1] + bb1;
                if (headed) {
                    int b = m >> 11, t = m & 2047;
                    int h = colb >> 6, d = colb & 63;
                    *(float2*)&out[((size_t)((b << 4) + h) * T_ + t) * HD_ + d] = o;
                } else {
                    *(float2*)&out[(size_t)m * N + colb] = o;
                }
            }
        }
    }
}

// ---------------- tensor-core flash attention with RL mask ----------------
// mask: allowed iff (col <= row) && (col % 25 != 24)
// CTA: 128 q-rows of one (b,h). 8 warps x 16 rows. kv tiles of 64.
// tf32 mma m16n8k8 for S=QK^T and O+=PV; online softmax in C fragments.
// Smem (tf32 bits, k-permuted in 16-groups, row stride 68):
//   qs[128][68], ks[64][68] ([key][d]), vs[64][68] ([d][key]), ps[128][68]
#define AS_ 68
__global__ __launch_bounds__(256) void attn_mma(
    const float* __restrict__ Q, const float* __restrict__ Km,
    const float* __restrict__ Vm, float* __restrict__ y)
{
    extern __shared__ uint32_t sm[];
    uint32_t* qs = sm;                   // 128*68
    uint32_t* ks = qs + 128 * AS_;       // 64*68
    uint32_t* vs = ks + 64 * AS_;        // 64*68
    uint32_t* ps = vs + 64 * AS_;        // 128*68

    int tid = threadIdx.x;
    int lane = tid & 31, w = tid >> 5;
    int r = lane >> 2, q4 = lane & 3;
    int qb = blockIdx.x, h = blockIdx.y, b = blockIdx.z;
    int i0 = qb * 128;

    const float* qg = Q + ((size_t)(b * H_ + h) * T_ + i0) * HD_;
    const float* kg = Km + (size_t)(b * H_ + h) * T_ * HD_;
    const float* vg = Vm + (size_t)(b * H_ + h) * T_ * HD_;

    // ---- stage Q tile (tf32, k-permuted) ----
#pragma unroll
    for (int l = 0; l < 8; l++) {
        int fi = tid + l * 256;              // 2048 float4s
        int row = fi >> 4;
        int kq = (fi & 15) << 2;
        float4 t4 = *(const float4*)(qg + row * 64 + kq);
        int base = row * AS_ + ((kq >> 4) << 4) + ((kq & 15) >> 2);
        qs[base + 0]  = f2tf32(t4.x);
        qs[base + 4]  = f2tf32(t4.y);
        qs[base + 8]  = f2tf32(t4.z);
        qs[base + 12] = f2tf32(t4.w);
    }
    __syncthreads();

    // persistent Q A-fragments (rows w*16 + r / +8, all 64 k)
    uint4 aQlo[4], aQhi[4];
    int qrow = (w * 16 + r) * AS_;
#pragma unroll
    for (int g = 0; g < 4; g++) {
        aQlo[g] = *(const uint4*)&qs[qrow + g * 16 + q4 * 4];
        aQhi[g] = *(const uint4*)&qs[qrow + 8 * AS_ + g * 16 + q4 * 4];
    }

    float acc[8][4] = {};
    float M0 = -1e30f, M1 = -1e30f, L0 = 0.f, L1 = 0.f;
    const float scale = 0.125f;
    int rg0 = i0 + w * 16 + r, rg1 = rg0 + 8;

    int nt = 2 * qb + 2;
    for (int t = 0; t < nt; t++) {
        int j0 = t * 64;
        // ---- stage K [key][d-perm] and V [d][key-perm] ----
#pragma unroll
        for (int l = 0; l < 4; l++) {
            int fi = tid + l * 256;          // 1024 float4s
            int row = fi >> 4;
            int kq = (fi & 15) << 2;
            float4 t4 = *(const float4*)(kg + (size_t)(j0 + row) * 64 + kq);
            int base = row * AS_ + ((kq >> 4) << 4) + ((kq & 15) >> 2);
            ks[base + 0]  = f2tf32(t4.x);
            ks[base + 4]  = f2tf32(t4.y);
            ks[base + 8]  = f2tf32(t4.z);
            ks[base + 12] = f2tf32(t4.w);
            // V transpose: element (key=row, d=kq+j) -> vs[d][perm(key)]
            float4 v4 = *(const float4*)(vg + (size_t)(j0 + row) * 64 + kq);
            int kp = ((row >> 4) << 4) + (row & 3) * 4 + ((row & 15) >> 2);
            vs[(kq + 0) * AS_ + kp] = f2tf32(v4.x);
            vs[(kq + 1) * AS_ + kp] = f2tf32(v4.y);
            vs[(kq + 2) * AS_ + kp] = f2tf32(v4.z);
            vs[(kq + 3) * AS_ + kp] = f2tf32(v4.w);
        }
        __syncthreads();

        // ---- S = Q K^T : 8 n-blocks x 4 k-groups x 2 ----
        float s[8][4] = {};
#pragma unroll
        for (int nb = 0; nb < 8; nb++) {
            int krow = (nb * 8 + r) * AS_;
#pragma unroll
            for (int g = 0; g < 4; g++) {
                uint4 bb = *(const uint4*)&ks[krow + g * 16 + q4 * 4];
                mma_tf32_k8(s[nb], aQlo[g].x, aQhi[g].x, aQlo[g].y, aQhi[g].y,
                            bb.x, bb.y);
                mma_tf32_k8(s[nb], aQlo[g].z, aQhi[g].z, aQlo[g].w, aQhi[g].w,
                            bb.z, bb.w);
            }
        }

        // ---- mask + scale; row max ----
        float m0 = -1e30f, m1 = -1e30f;
#pragma unroll
        for (int nb = 0; nb < 8; nb++) {
            int c0 = j0 + nb * 8 + q4 * 2;
            bool cm0 = ((c0) % 25) != 24;
            bool cm1 = ((c0 + 1) % 25) != 24;
            s[nb][0] = (cm0 && c0 <= rg0)     ? s[nb][0] * scale : -1e30f;
            s[nb][1] = (cm1 && c0 + 1 <= rg0) ? s[nb][1] * scale : -1e30f;
            s[nb][2] = (cm0 && c0 <= rg1)     ? s[nb][2] * scale : -1e30f;
            s[nb][3] = (cm1 && c0 + 1 <= rg1) ? s[nb][3] * scale : -1e30f;
            m0 = fmaxf(m0, fmaxf(s[nb][0], s[nb][1]));
            m1 = fmaxf(m1, fmaxf(s[nb][2], s[nb][3]));
        }
#pragma unroll
        for (int o = 1; o <= 2; o <<= 1) {
            m0 = fmaxf(m0, __shfl_xor_sync(0xffffffffu, m0, o));
            m1 = fmaxf(m1, __shfl_xor_sync(0xffffffffu, m1, o));
        }

        // ---- online softmax update ----
        float Mn0 = fmaxf(M0, m0), Mn1 = fmaxf(M1, m1);
        float al0 = __expf(M0 - Mn0), al1 = __expf(M1 - Mn1);
        M0 = Mn0; M1 = Mn1;
        float rs0 = 0.f, rs1 = 0.f;
#pragma unroll
        for (int nb = 0; nb < 8; nb++) {
            float p0 = __expf(s[nb][0] - Mn0);
            float p1 = __expf(s[nb][1] - Mn0);
            float p2 = __expf(s[nb][2] - Mn1);
            float p3 = __expf(s[nb][3] - Mn1);
            s[nb][0] = p0; s[nb][1] = p1; s[nb][2] = p2; s[nb][3] = p3;
            rs0 += p0 + p1; rs1 += p2 + p3;
        }
#pragma unroll
        for (int o = 1; o <= 2; o <<= 1) {
            rs0 += __shfl_xor_sync(0xffffffffu, rs0, o);
            rs1 += __shfl_xor_sync(0xffffffffu, rs1, o);
        }
        L0 = L0 * al0 + rs0;
        L1 = L1 * al1 + rs1;
#pragma unroll
        for (int db = 0; db < 8; db++) {
            acc[db][0] *= al0; acc[db][1] *= al0;
            acc[db][2] *= al1; acc[db][3] *= al1;
        }

        // ---- stage P (tf32, k-permuted), warp-local ----
#pragma unroll
        for (int nb = 0; nb < 8; nb++) {
#pragma unroll
            for (int e = 0; e < 2; e++) {
                int kk = nb * 8 + q4 * 2 + e;
                int pos = ((kk >> 4) << 4) + (kk & 3) * 4 + ((kk & 15) >> 2);
                ps[qrow + pos] = f2tf32(s[nb][e]);
                ps[qrow + 8 * AS_ + pos] = f2tf32(s[nb][2 + e]);
            }
        }
        __syncwarp();

        // ---- O += P V ----
#pragma unroll
        for (int g = 0; g < 4; g++) {
            uint4 plo = *(const uint4*)&ps[qrow + g * 16 + q4 * 4];
            uint4 phi = *(const uint4*)&ps[qrow + 8 * AS_ + g * 16 + q4 * 4];
#pragma unroll
            for (int db = 0; db < 8; db++) {
                uint4 bb = *(const uint4*)&vs[(db * 8 + r) * AS_ + g * 16 + q4 * 4];
                mma_tf32_k8(acc[db], plo.x, phi.x, plo.y, phi.y, bb.x, bb.y);
                mma_tf32_k8(acc[db], plo.z, phi.z, plo.w, phi.w, bb.z, bb.w);
            }
        }
        __syncthreads();   // protect ks/vs before next tile's stores
    }

    // ---- epilogue: normalize, write y[B,T,C] ----
    float inv0 = 1.0f / L0, inv1 = 1.0f / L1;
#pragma unroll
    for (int db = 0; db < 8; db++) {
        int c = h * 64 + db * 8 + q4 * 2;
        float2 o0, o1;
        o0.x = acc[db][0] * inv0; o0.y = acc[db][1] * inv0;
        o1.x = acc[db][2] * inv1; o1.y = acc[db][3] * inv1;
        *(float2*)&y[((size_t)(b * T_) + rg0) * C_ + c] = o0;
        *(float2*)&y[((size_t)(b * T_) + rg1) * C_ + c] = o1;
    }
}

// ---------------- launch ----------------
extern "C" void kernel_launch(void* const* d_in, const int* in_sizes, int n_in,
                              void* d_out, int out_size) {
    const float* x  = (const float*)d_in[0];
    const float* Wq = (const float*)d_in[1];
    const float* bq = (const float*)d_in[2];
    const float* Wk = (const float*)d_in[3];
    const float* bk = (const float*)d_in[4];
    const float* Wv = (const float*)d_in[5];
    const float* bv = (const float*)d_in[6];
    const float* Wp = (const float*)d_in[7];
    const float* bp = (const float*)d_in[8];

    float *q, *k, *v, *y;
    cudaGetSymbolAddress((void**)&q, g_q);
    cudaGetSymbolAddress((void**)&k, g_k);
    cudaGetSymbolAddress((void**)&v, g_v);
    cudaGetSymbolAddress((void**)&y, g_y);

    dim3 gg(8, 64);  // N/128, M/128 with M = B*T = 8192
    gemm_tf32<<<gg, 256>>>(x, Wq, bq, q, 1);
    gemm_tf32<<<gg, 256>>>(x, Wk, bk, k, 1);
    gemm_tf32<<<gg, 256>>>(x, Wv, bv, v, 1);

    const int ATT_SMEM = (128 + 64 + 64 + 128) * AS_ * (int)sizeof(uint32_t); // 104448
    cudaFuncSetAttribute(attn_mma, cudaFuncAttributeMaxDynamicSharedMemorySize, ATT_SMEM);
    attn_mma<<<dim3(T_ / 128, H_, B_), 256, ATT_SMEM>>>(q, k, v, y);

    gemm_tf32<<<gg, 256>>>(y, Wp, bp, (float*)d_out, 0);
}

// round 12
// speedup vs baseline: 2.6652x; 1.2805x over previous
#include <cuda_runtime.h>
#include <cuda_bf16.h>
#include <cstdint>

#define B_ 4
#define T_ 2048
#define C_ 1024
#define H_ 16
#define HD_ 64

// ---------------- scratch (allocation-free: __device__ globals) ----------------
__device__ float g_q[B_*H_*T_*HD_];   // 32 MB  [B,H,T,HD]
__device__ float g_k[B_*H_*T_*HD_];   // 32 MB
__device__ float g_v[B_*H_*T_*HD_];   // 32 MB
__device__ float g_y[B_*T_*C_];       // 32 MB  [B,T,C]

// ---------------- helpers ----------------
__device__ __forceinline__ uint32_t f2tf32(float x) {
    uint32_t r;
    asm("cvt.rna.tf32.f32 %0, %1;" : "=r"(r) : "f"(x));
    return r;
}

__device__ __forceinline__ void mma_tf32_k8(
    float* c, uint32_t a0, uint32_t a1, uint32_t a2, uint32_t a3,
    uint32_t b0, uint32_t b1)
{
    asm volatile(
        "mma.sync.aligned.m16n8k8.row.col.f32.tf32.tf32.f32 "
        "{%0,%1,%2,%3}, {%4,%5,%6,%7}, {%8,%9}, {%0,%1,%2,%3};"
        : "+f"(c[0]), "+f"(c[1]), "+f"(c[2]), "+f"(c[3])
        : "r"(a0), "r"(a1), "r"(a2), "r"(a3), "r"(b0), "r"(b1));
}

// granule XOR swizzle: row bit0^bit2 -> bit2 (phase separation for frag loads
// AND d-spread for transposed V stores), bits 3,4 -> bits 1,0 (store spread).
__device__ __forceinline__ int swz_(int row) {
    return ((((row) ^ ((row) >> 2)) & 1) << 2)
         | ((((row) >> 3) & 1) << 1)
         | (((row) >> 4) & 1);
}
#define RS_ 64

// ---------------- tf32 GEMM: out = A[M,1024] @ W^T + bias ----------------
// Double-buffered smem + register prefetch; QKV fused via blockIdx.z.
__global__ __launch_bounds__(256) void gemm_tf32(
    const float* __restrict__ A,
    const float* __restrict__ W0, const float* __restrict__ bv0, float* __restrict__ o0,
    const float* __restrict__ W1, const float* __restrict__ bv1, float* __restrict__ o1,
    const float* __restrict__ W2, const float* __restrict__ bv2, float* __restrict__ o2,
    int headed)
{
    const float* W = W0; const float* bias = bv0; float* out = o0;
    if (blockIdx.z == 1) { W = W1; bias = bv1; out = o1; }
    else if (blockIdx.z == 2) { W = W2; bias = bv2; out = o2; }

    const int K = 1024, N = 1024;
    __shared__ uint32_t As[2][128 * 16];
    __shared__ uint32_t Bs[2][128 * 16];

    int tid = threadIdx.x;
    int lane = tid & 31, warp = tid >> 5;
    int wm = warp & 1, wn = warp >> 1;     // 2 (M) x 4 (N)
    int m0 = blockIdx.y * 128, n0 = blockIdx.x * 128;
    int r = lane >> 2, q = lane & 3;

    float acc[16][4] = {};
    float4 avr[2], bvr[2];

    // prologue: load k0=0 tile to regs, stage into buf 0
#pragma unroll
    for (int l = 0; l < 2; l++) {
        int fi = tid + l * 256;
        int row = fi >> 2, kq = (fi & 3) << 2;
        avr[l] = *(const float4*)(A + (size_t)(m0 + row) * K + kq);
        bvr[l] = *(const float4*)(W + (size_t)(n0 + row) * K + kq);
    }
#pragma unroll
    for (int l = 0; l < 2; l++) {
        int fi = tid + l * 256;
        int row = fi >> 2, kq = (fi & 3) << 2;
        int base = row * 16 + (kq >> 2);
        As[0][base + 0]  = f2tf32(avr[l].x);
        As[0][base + 4]  = f2tf32(avr[l].y);
        As[0][base + 8]  = f2tf32(avr[l].z);
        As[0][base + 12] = f2tf32(avr[l].w);
        Bs[0][base + 0]  = f2tf32(bvr[l].x);
        Bs[0][base + 4]  = f2tf32(bvr[l].y);
        Bs[0][base + 8]  = f2tf32(bvr[l].z);
        Bs[0][base + 12] = f2tf32(bvr[l].w);
    }
    __syncthreads();

    for (int k0 = 0; k0 < K; k0 += 16) {
        int cur = (k0 >> 4) & 1;
        if (k0 + 16 < K) {
#pragma unroll
            for (int l = 0; l < 2; l++) {
                int fi = tid + l * 256;
                int row = fi >> 2, kq = (fi & 3) << 2;
                avr[l] = *(const float4*)(A + (size_t)(m0 + row) * K + k0 + 16 + kq);
                bvr[l] = *(const float4*)(W + (size_t)(n0 + row) * K + k0 + 16 + kq);
            }
        }

        uint4 aLo[4], aHi[4], bV[4];
#pragma unroll
        for (int mt = 0; mt < 4; mt++) {
            int row = wm * 64 + mt * 16 + r;
            aLo[mt] = *(const uint4*)&As[cur][row * 16 + q * 4];
            aHi[mt] = *(const uint4*)&As[cur][(row + 8) * 16 + q * 4];
        }
#pragma unroll
        for (int nt = 0; nt < 4; nt++) {
            int col = wn * 32 + nt * 8 + r;
            bV[nt] = *(const uint4*)&Bs[cur][col * 16 + q * 4];
        }

#pragma unroll
        for (int mt = 0; mt < 4; mt++)
#pragma unroll
            for (int nt = 0; nt < 4; nt++) {
                float* c = acc[mt * 4 + nt];
                mma_tf32_k8(c, aLo[mt].x, aHi[mt].x, aLo[mt].y, aHi[mt].y,
                            bV[nt].x, bV[nt].y);
                mma_tf32_k8(c, aLo[mt].z, aHi[mt].z, aLo[mt].w, aHi[mt].w,
                            bV[nt].z, bV[nt].w);
            }

        if (k0 + 16 < K) {
            int nxt = cur ^ 1;
#pragma unroll
            for (int l = 0; l < 2; l++) {
                int fi = tid + l * 256;
                int row = fi >> 2, kq = (fi & 3) << 2;
                int base = row * 16 + (kq >> 2);
                As[nxt][base + 0]  = f2tf32(avr[l].x);
                As[nxt][base + 4]  = f2tf32(avr[l].y);
                As[nxt][base + 8]  = f2tf32(avr[l].z);
                As[nxt][base + 12] = f2tf32(avr[l].w);
                Bs[nxt][base + 0]  = f2tf32(bvr[l].x);
                Bs[nxt][base + 4]  = f2tf32(bvr[l].y);
                Bs[nxt][base + 8]  = f2tf32(bvr[l].z);
                Bs[nxt][base + 12] = f2tf32(bvr[l].w);
            }
        }
        __syncthreads();
    }

#pragma unroll
    for (int mt = 0; mt < 4; mt++) {
        int rowb = m0 + wm * 64 + mt * 16 + r;
#pragma unroll
        for (int nt = 0; nt < 4; nt++) {
            int colb = n0 + wn * 32 + nt * 8 + q * 2;
            float bb0 = bias[colb], bb1 = bias[colb + 1];
            float* c = acc[mt * 4 + nt];
#pragma unroll
            for (int hh = 0; hh < 2; hh++) {
                int m = rowb + hh * 8;
                float2 o;
                o.x = c[hh * 2 + 0] + bb0;
                o.y = c[hh * 2 + 1] + bb1;
                if (headed) {
                    int b = m >> 11, t = m & 2047;
                    int h = colb >> 6, d = colb & 63;
                    *(float2*)&out[((size_t)((b << 4) + h) * T_ + t) * HD_ + d] = o;
                } else {
                    *(float2*)&out[(size_t)m * N + colb] = o;
                }
            }
        }
    }
}

// ---------------- stage K [key][d] + V-transposed [d][key] (swizzled) --------
__device__ __forceinline__ void stage_kv(
    uint32_t* __restrict__ ks, uint32_t* __restrict__ vs,
    const float4* kreg, const float4* vreg, int tid)
{
#pragma unroll
    for (int l = 0; l < 4; l++) {
        int fi = tid + l * 256;
        int row = fi >> 4, kq = (fi & 15) << 2;
        int g = kq >> 4, wrd = (kq >> 2) & 3, sw = swz_(row);
        uint32_t* p = &ks[row * RS_ + wrd];
        p[((((g << 2) | 0) ^ sw) << 2)] = f2tf32(kreg[l].x);
        p[((((g << 2) | 1) ^ sw) << 2)] = f2tf32(kreg[l].y);
        p[((((g << 2) | 2) ^ sw) << 2)] = f2tf32(kreg[l].z);
        p[((((g << 2) | 3) ^ sw) << 2)] = f2tf32(kreg[l].w);
        // V transpose: (key=row, d=kq+j) -> vs[d][key]
        int gk = ((row >> 4) << 2) | (row & 3);
        int wk = (row >> 2) & 3;
        vs[(kq + 0) * RS_ + (((gk ^ swz_(kq + 0)) << 2) + wk)] = f2tf32(vreg[l].x);
        vs[(kq + 1) * RS_ + (((gk ^ swz_(kq + 1)) << 2) + wk)] = f2tf32(vreg[l].y);
        vs[(kq + 2) * RS_ + (((gk ^ swz_(kq + 2)) << 2) + wk)] = f2tf32(vreg[l].z);
        vs[(kq + 3) * RS_ + (((gk ^ swz_(kq + 3)) << 2) + wk)] = f2tf32(vreg[l].w);
    }
}

// ---------------- tensor-core flash attention with RL mask ----------------
// mask: allowed iff (col <= row) && (col % 25 != 24)
// CTA: 128 q-rows of one (b,h); 8 warps x 16 rows; kv tiles of 64.
// Double-buffered K/V with register prefetch; XOR-swizzled smem (stride 64).
__global__ __launch_bounds__(256) void attn_mma(
    const float* __restrict__ Q, const float* __restrict__ Km,
    const float* __restrict__ Vm, float* __restrict__ y)
{
    extern __shared__ uint32_t sm[];
    uint32_t* qs  = sm;                     // 128*64
    uint32_t* ksB = qs + 128 * RS_;         // 2 * 64*64
    uint32_t* vsB = ksB + 2 * 64 * RS_;     // 2 * 64*64
    uint32_t* ps  = vsB + 2 * 64 * RS_;     // 128*64

    int tid = threadIdx.x;
    int lane = tid & 31, w = tid >> 5;
    int r = lane >> 2, q4 = lane & 3;
    int qb = blockIdx.x, h = blockIdx.y, b = blockIdx.z;
    int i0 = qb * 128;

    const float* qg = Q + ((size_t)(b * H_ + h) * T_ + i0) * HD_;
    const float* kg = Km + (size_t)(b * H_ + h) * T_ * HD_;
    const float* vg = Vm + (size_t)(b * H_ + h) * T_ * HD_;

    // ---- stage Q (swizzled) ----
#pragma unroll
    for (int l = 0; l < 8; l++) {
        int fi = tid + l * 256;
        int row = fi >> 4, kq = (fi & 15) << 2;
        float4 t4 = *(const float4*)(qg + row * 64 + kq);
        int g = kq >> 4, wrd = (kq >> 2) & 3, sw = swz_(row);
        uint32_t* p = &qs[row * RS_ + wrd];
        p[((((g << 2) | 0) ^ sw) << 2)] = f2tf32(t4.x);
        p[((((g << 2) | 1) ^ sw) << 2)] = f2tf32(t4.y);
        p[((((g << 2) | 2) ^ sw) << 2)] = f2tf32(t4.z);
        p[((((g << 2) | 3) ^ sw) << 2)] = f2tf32(t4.w);
    }

    int nt = 2 * qb + 2;
    float4 kreg[4], vreg[4];
    // prologue: load kv tile 0
#pragma unroll
    for (int l = 0; l < 4; l++) {
        int fi = tid + l * 256;
        int row = fi >> 4, kq = (fi & 15) << 2;
        kreg[l] = *(const float4*)(kg + (size_t)row * 64 + kq);
        vreg[l] = *(const float4*)(vg + (size_t)row * 64 + kq);
    }
    stage_kv(ksB, vsB, kreg, vreg, tid);
    __syncthreads();

    // persistent Q fragments
    int myr = w * 16 + r;
    int sw0 = swz_(myr), sw8 = swz_(myr + 8);
    uint4 aQlo[4], aQhi[4];
#pragma unroll
    for (int g = 0; g < 4; g++) {
        aQlo[g] = *(const uint4*)&qs[myr * RS_ + ((((g << 2) | q4) ^ sw0) << 2)];
        aQhi[g] = *(const uint4*)&qs[(myr + 8) * RS_ + ((((g << 2) | q4) ^ sw8) << 2)];
    }

    float acc[8][4] = {};
    float M0 = -1e30f, M1 = -1e30f, L0 = 0.f, L1 = 0.f;
    const float scale = 0.125f;
    int rg0 = i0 + myr, rg1 = rg0 + 8;

    for (int t = 0; t < nt; t++) {
        int cur = t & 1;
        uint32_t* ks = ksB + cur * 64 * RS_;
        uint32_t* vs = vsB + cur * 64 * RS_;

        // prefetch next tile into registers
        if (t + 1 < nt) {
            int j0n = (t + 1) * 64;
#pragma unroll
            for (int l = 0; l < 4; l++) {
                int fi = tid + l * 256;
                int row = fi >> 4, kq = (fi & 15) << 2;
                kreg[l] = *(const float4*)(kg + (size_t)(j0n + row) * 64 + kq);
                vreg[l] = *(const float4*)(vg + (size_t)(j0n + row) * 64 + kq);
            }
        }
        int j0 = t * 64;

        // ---- S = Q K^T ----
        float s[8][4] = {};
#pragma unroll
        for (int nb = 0; nb < 8; nb++) {
            int krow = nb * 8 + r;
            const uint32_t* kb2 = &ks[krow * RS_];
            int swk = swz_(krow);
#pragma unroll
            for (int g = 0; g < 4; g++) {
                uint4 bb = *(const uint4*)&kb2[(((g << 2) | q4) ^ swk) << 2];
                mma_tf32_k8(s[nb], aQlo[g].x, aQhi[g].x, aQlo[g].y, aQhi[g].y,
                            bb.x, bb.y);
                mma_tf32_k8(s[nb], aQlo[g].z, aQhi[g].z, aQlo[g].w, aQhi[g].w,
                            bb.z, bb.w);
            }
        }

        // ---- mask + scale; row max ----
        float m0 = -1e30f, m1 = -1e30f;
#pragma unroll
        for (int nb = 0; nb < 8; nb++) {
            int c0 = j0 + nb * 8 + q4 * 2;
            bool cm0 = ((c0) % 25) != 24;
            bool cm1 = ((c0 + 1) % 25) != 24;
            s[nb][0] = (cm0 && c0 <= rg0)     ? s[nb][0] * scale : -1e30f;
            s[nb][1] = (cm1 && c0 + 1 <= rg0) ? s[nb][1] * scale : -1e30f;
            s[nb][2] = (cm0 && c0 <= rg1)     ? s[nb][2] * scale : -1e30f;
            s[nb][3] = (cm1 && c0 + 1 <= rg1) ? s[nb][3] * scale : -1e30f;
            m0 = fmaxf(m0, fmaxf(s[nb][0], s[nb][1]));
            m1 = fmaxf(m1, fmaxf(s[nb][2], s[nb][3]));
        }
#pragma unroll
        for (int o = 1; o <= 2; o <<= 1) {
            m0 = fmaxf(m0, __shfl_xor_sync(0xffffffffu, m0, o));
            m1 = fmaxf(m1, __shfl_xor_sync(0xffffffffu, m1, o));
        }

        // ---- online softmax ----
        float Mn0 = fmaxf(M0, m0), Mn1 = fmaxf(M1, m1);
        float al0 = __expf(M0 - Mn0), al1 = __expf(M1 - Mn1);
        M0 = Mn0; M1 = Mn1;
        float rs0 = 0.f, rs1 = 0.f;
#pragma unroll
        for (int nb = 0; nb < 8; nb++) {
            float p0 = __expf(s[nb][0] - Mn0);
            float p1 = __expf(s[nb][1] - Mn0);
            float p2 = __expf(s[nb][2] - Mn1);
            float p3 = __expf(s[nb][3] - Mn1);
            s[nb][0] = p0; s[nb][1] = p1; s[nb][2] = p2; s[nb][3] = p3;
            rs0 += p0 + p1; rs1 += p2 + p3;
        }
#pragma unroll
        for (int o = 1; o <= 2; o <<= 1) {
            rs0 += __shfl_xor_sync(0xffffffffu, rs0, o);
            rs1 += __shfl_xor_sync(0xffffffffu, rs1, o);
        }
        L0 = L0 * al0 + rs0;
        L1 = L1 * al1 + rs1;
#pragma unroll
        for (int db = 0; db < 8; db++) {
            acc[db][0] *= al0; acc[db][1] *= al0;
            acc[db][2] *= al1; acc[db][3] *= al1;
        }

        // ---- stage P (warp-local rows, swizzled) ----
#pragma unroll
        for (int nb = 0; nb < 8; nb++) {
#pragma unroll
            for (int e = 0; e < 2; e++) {
                int kk = nb * 8 + q4 * 2 + e;
                int gq = ((kk >> 4) << 2) | (kk & 3);
                int wd = (kk >> 2) & 3;
                ps[myr * RS_ + (((gq ^ sw0) << 2) + wd)] = f2tf32(s[nb][e]);
                ps[(myr + 8) * RS_ + (((gq ^ sw8) << 2) + wd)] = f2tf32(s[nb][2 + e]);
            }
        }
        __syncwarp();

        // ---- O += P V ----
#pragma unroll
        for (int g = 0; g < 4; g++) {
            uint4 plo = *(const uint4*)&ps[myr * RS_ + ((((g << 2) | q4) ^ sw0) << 2)];
            uint4 phi = *(const uint4*)&ps[(myr + 8) * RS_ + ((((g << 2) | q4) ^ sw8) << 2)];
#pragma unroll
            for (int db = 0; db < 8; db++) {
                int vrow = db * 8 + r;
                uint4 bb = *(const uint4*)&vs[vrow * RS_ + ((((g << 2) | q4) ^ swz_(vrow)) << 2)];
                mma_tf32_k8(acc[db], plo.x, phi.x, plo.y, phi.y, bb.x, bb.y);
                mma_tf32_k8(acc[db], plo.z, phi.z, plo.w, phi.w, bb.z, bb.w);
            }
        }

        // ---- store prefetched tile into the other buffer ----
        if (t + 1 < nt) {
            stage_kv(ksB + (cur ^ 1) * 64 * RS_, vsB + (cur ^ 1) * 64 * RS_,
                     kreg, vreg, tid);
        }
        __syncthreads();
    }

    // ---- epilogue: normalize, write y[B,T,C] ----
    float inv0 = 1.0f / L0, inv1 = 1.0f / L1;
#pragma unroll
    for (int db = 0; db < 8; db++) {
        int c = h * 64 + db * 8 + q4 * 2;
        float2 o0, o1;
        o0.x = acc[db][0] * inv0; o0.y = acc[db][1] * inv0;
        o1.x = acc[db][2] * inv1; o1.y = acc[db][3] * inv1;
        *(float2*)&y[((size_t)(b * T_) + rg0) * C_ + c] = o0;
        *(float2*)&y[((size_t)(b * T_) + rg1) * C_ + c] = o1;
    }
}

// ---------------- launch ----------------
extern "C" void kernel_launch(void* const* d_in, const int* in_sizes, int n_in,
                              void* d_out, int out_size) {
    const float* x  = (const float*)d_in[0];
    const float* Wq = (const float*)d_in[1];
    const float* bq = (const float*)d_in[2];
    const float* Wk = (const float*)d_in[3];
    const float* bk = (const float*)d_in[4];
    const float* Wv = (const float*)d_in[5];
    const float* bv = (const float*)d_in[6];
    const float* Wp = (const float*)d_in[7];
    const float* bp = (const float*)d_in[8];

    float *q, *k, *v, *y;
    cudaGetSymbolAddress((void**)&q, g_q);
    cudaGetSymbolAddress((void**)&k, g_k);
    cudaGetSymbolAddress((void**)&v, g_v);
    cudaGetSymbolAddress((void**)&y, g_y);

    // fused QKV projections (blockIdx.z selects weight set)
    dim3 gqkv(8, 64, 3);
    gemm_tf32<<<gqkv, 256>>>(x, Wq, bq, q, Wk, bk, k, Wv, bv, v, 1);

    const int ATT_SMEM = (128 + 128 + 128 + 128) * RS_ * (int)sizeof(uint32_t); // 131072
    cudaFuncSetAttribute(attn_mma, cudaFuncAttributeMaxDynamicSharedMemorySize, ATT_SMEM);
    attn_mma<<<dim3(T_ / 128, H_, B_), 256, ATT_SMEM>>>(q, k, v, y);

    dim3 gp(8, 64, 1);
    gemm_tf32<<<gp, 256>>>(y, Wp, bp, (float*)d_out,
                           Wp, bp, (float*)d_out, Wp, bp, (float*)d_out, 0);
}

// round 13
// speedup vs baseline: 2.8319x; 1.0625x over previous
#include <cuda_runtime.h>
#include <cuda_bf16.h>
#include <cstdint>

#define B_ 4
#define T_ 2048
#define C_ 1024
#define H_ 16
#define HD_ 64

// ---------------- scratch (allocation-free: __device__ globals) ----------------
__device__ float g_q[B_*H_*T_*HD_];   // 32 MB  [B,H,T,HD]
__device__ float g_k[B_*H_*T_*HD_];   // 32 MB
__device__ float g_v[B_*H_*T_*HD_];   // 32 MB
__device__ float g_y[B_*T_*C_];       // 32 MB  [B,T,C]

// ---------------- helpers ----------------
__device__ __forceinline__ uint32_t f2tf32(float x) {
    uint32_t r;
    asm("cvt.rna.tf32.f32 %0, %1;" : "=r"(r) : "f"(x));
    return r;
}

__device__ __forceinline__ void mma_tf32_k8(
    float* c, uint32_t a0, uint32_t a1, uint32_t a2, uint32_t a3,
    uint32_t b0, uint32_t b1)
{
    asm volatile(
        "mma.sync.aligned.m16n8k8.row.col.f32.tf32.tf32.f32 "
        "{%0,%1,%2,%3}, {%4,%5,%6,%7}, {%8,%9}, {%0,%1,%2,%3};"
        : "+f"(c[0]), "+f"(c[1]), "+f"(c[2]), "+f"(c[3])
        : "r"(a0), "r"(a1), "r"(a2), "r"(a3), "r"(b0), "r"(b1));
}

// attn swizzle (stride-64 rows, 16 granules of 4 words)
__device__ __forceinline__ int swz_(int row) {
    return ((((row) ^ ((row) >> 2)) & 1) << 2)
         | ((((row) >> 3) & 1) << 1)
         | (((row) >> 4) & 1);
}
#define RS_ 64

// GEMM swizzle (stride-16 rows, 4 granules of 4 words): granule ^= (row>>1)&3
__device__ __forceinline__ int gsw_(int row) { return (row >> 1) & 3; }

// ---------------- tf32 GEMM: out = A[M,1024] @ W^T + bias ----------------
// Double-buffered smem + register prefetch; QKV fused via blockIdx.z.
// Smem tile [row][16 words], granule-XOR swizzled: conflict-free staging
// stores AND conflict-free fragment LDS.128.
__global__ __launch_bounds__(256) void gemm_tf32(
    const float* __restrict__ A,
    const float* __restrict__ W0, const float* __restrict__ bv0, float* __restrict__ o0,
    const float* __restrict__ W1, const float* __restrict__ bv1, float* __restrict__ o1,
    const float* __restrict__ W2, const float* __restrict__ bv2, float* __restrict__ o2,
    int headed)
{
    const float* W = W0; const float* bias = bv0; float* out = o0;
    if (blockIdx.z == 1) { W = W1; bias = bv1; out = o1; }
    else if (blockIdx.z == 2) { W = W2; bias = bv2; out = o2; }

    const int K = 1024, N = 1024;
    __shared__ uint32_t As[2][128 * 16];
    __shared__ uint32_t Bs[2][128 * 16];

    int tid = threadIdx.x;
    int lane = tid & 31, warp = tid >> 5;
    int wm = warp & 1, wn = warp >> 1;     // 2 (M) x 4 (N)
    int m0 = blockIdx.y * 128, n0 = blockIdx.x * 128;
    int r = lane >> 2, q = lane & 3;
    int sfr = gsw_(r);                     // fragment swizzle (rows mult-8 based)

    float acc[16][4] = {};
    float4 avr[2], bvr[2];

    // staging positions for this thread (fi = tid + l*256)
    int srow[2], sbase[2][4];
#pragma unroll
    for (int l = 0; l < 2; l++) {
        int fi = tid + l * 256;
        srow[l] = fi >> 2;
        int w = fi & 3;                     // k>>2 of this float4 group
        int sg = gsw_(srow[l]);
#pragma unroll
        for (int j = 0; j < 4; j++)         // value j has k&3 == j
            sbase[l][j] = srow[l] * 16 + (((j ^ sg) & 3) << 2) + w;
    }

    // prologue: load k0=0 tile to regs, stage into buf 0
#pragma unroll
    for (int l = 0; l < 2; l++) {
        avr[l] = *(const float4*)(A + (size_t)(m0 + srow[l]) * K + ((tid + l*256) & 3) * 4);
        bvr[l] = *(const float4*)(W + (size_t)(n0 + srow[l]) * K + ((tid + l*256) & 3) * 4);
    }
#pragma unroll
    for (int l = 0; l < 2; l++) {
        As[0][sbase[l][0]] = f2tf32(avr[l].x);
        As[0][sbase[l][1]] = f2tf32(avr[l].y);
        As[0][sbase[l][2]] = f2tf32(avr[l].z);
        As[0][sbase[l][3]] = f2tf32(avr[l].w);
        Bs[0][sbase[l][0]] = f2tf32(bvr[l].x);
        Bs[0][sbase[l][1]] = f2tf32(bvr[l].y);
        Bs[0][sbase[l][2]] = f2tf32(bvr[l].z);
        Bs[0][sbase[l][3]] = f2tf32(bvr[l].w);
    }
    __syncthreads();

    for (int k0 = 0; k0 < K; k0 += 16) {
        int cur = (k0 >> 4) & 1;
        if (k0 + 16 < K) {
#pragma unroll
            for (int l = 0; l < 2; l++) {
                int kq = ((tid + l*256) & 3) * 4;
                avr[l] = *(const float4*)(A + (size_t)(m0 + srow[l]) * K + k0 + 16 + kq);
                bvr[l] = *(const float4*)(W + (size_t)(n0 + srow[l]) * K + k0 + 16 + kq);
            }
        }

        uint4 aLo[4], aHi[4], bV[4];
#pragma unroll
        for (int mt = 0; mt < 4; mt++) {
            int row = wm * 64 + mt * 16 + r;
            aLo[mt] = *(const uint4*)&As[cur][row * 16 + ((q ^ sfr) << 2)];
            aHi[mt] = *(const uint4*)&As[cur][(row + 8) * 16 + ((q ^ sfr) << 2)];
        }
#pragma unroll
        for (int nt = 0; nt < 4; nt++) {
            int col = wn * 32 + nt * 8 + r;
            bV[nt] = *(const uint4*)&Bs[cur][col * 16 + ((q ^ sfr) << 2)];
        }

#pragma unroll
        for (int mt = 0; mt < 4; mt++)
#pragma unroll
            for (int nt = 0; nt < 4; nt++) {
                float* c = acc[mt * 4 + nt];
                mma_tf32_k8(c, aLo[mt].x, aHi[mt].x, aLo[mt].y, aHi[mt].y,
                            bV[nt].x, bV[nt].y);
                mma_tf32_k8(c, aLo[mt].z, aHi[mt].z, aLo[mt].w, aHi[mt].w,
                            bV[nt].z, bV[nt].w);
            }

        if (k0 + 16 < K) {
            int nxt = cur ^ 1;
#pragma unroll
            for (int l = 0; l < 2; l++) {
                As[nxt][sbase[l][0]] = f2tf32(avr[l].x);
                As[nxt][sbase[l][1]] = f2tf32(avr[l].y);
                As[nxt][sbase[l][2]] = f2tf32(avr[l].z);
                As[nxt][sbase[l][3]] = f2tf32(avr[l].w);
                Bs[nxt][sbase[l][0]] = f2tf32(bvr[l].x);
                Bs[nxt][sbase[l][1]] = f2tf32(bvr[l].y);
                Bs[nxt][sbase[l][2]] = f2tf32(bvr[l].z);
                Bs[nxt][sbase[l][3]] = f2tf32(bvr[l].w);
            }
        }
        __syncthreads();
    }

#pragma unroll
    for (int mt = 0; mt < 4; mt++) {
        int rowb = m0 + wm * 64 + mt * 16 + r;
#pragma unroll
        for (int nt = 0; nt < 4; nt++) {
            int colb = n0 + wn * 32 + nt * 8 + q * 2;
            float bb0 = bias[colb], bb1 = bias[colb + 1];
            float* c = acc[mt * 4 + nt];
#pragma unroll
            for (int hh = 0; hh < 2; hh++) {
                int m = rowb + hh * 8;
                float2 o;
                o.x = c[hh * 2 + 0] + bb0;
                o.y = c[hh * 2 + 1] + bb1;
                if (headed) {
                    int b = m >> 11, t = m & 2047;
                    int h = colb >> 6, d = colb & 63;
                    *(float2*)&out[((size_t)((b << 4) + h) * T_ + t) * HD_ + d] = o;
                } else {
                    *(float2*)&out[(size_t)m * N + colb] = o;
                }
            }
        }
    }
}

// ---------------- stage K [key][d] + V-transposed [d][key] (swizzled) --------
__device__ __forceinline__ void stage_kv(
    uint32_t* __restrict__ ks, uint32_t* __restrict__ vs,
    const float4* kreg, const float4* vreg, int tid)
{
#pragma unroll
    for (int l = 0; l < 4; l++) {
        int fi = tid + l * 256;
        int row = fi >> 4, kq = (fi & 15) << 2;
        int g = kq >> 4, wrd = (kq >> 2) & 3, sw = swz_(row);
        uint32_t* p = &ks[row * RS_ + wrd];
        p[((((g << 2) | 0) ^ sw) << 2)] = f2tf32(kreg[l].x);
        p[((((g << 2) | 1) ^ sw) << 2)] = f2tf32(kreg[l].y);
        p[((((g << 2) | 2) ^ sw) << 2)] = f2tf32(kreg[l].z);
        p[((((g << 2) | 3) ^ sw) << 2)] = f2tf32(kreg[l].w);
        // V transpose: (key=row, d=kq+j) -> vs[d][key]
        int gk = ((row >> 4) << 2) | (row & 3);
        int wk = (row >> 2) & 3;
        vs[(kq + 0) * RS_ + (((gk ^ swz_(kq + 0)) << 2) + wk)] = f2tf32(vreg[l].x);
        vs[(kq + 1) * RS_ + (((gk ^ swz_(kq + 1)) << 2) + wk)] = f2tf32(vreg[l].y);
        vs[(kq + 2) * RS_ + (((gk ^ swz_(kq + 2)) << 2) + wk)] = f2tf32(vreg[l].z);
        vs[(kq + 3) * RS_ + (((gk ^ swz_(kq + 3)) << 2) + wk)] = f2tf32(vreg[l].w);
    }
}

// ---------------- tensor-core flash attention with RL mask ----------------
// mask: allowed iff (col <= row) && (col % 25 != 24)
// CTA: 128 q-rows of one (b,h); 8 warps x 16 rows; kv tiles of 64.
// Q pre-scaled by 1/8 (exact power of 2) during staging.
__global__ __launch_bounds__(256) void attn_mma(
    const float* __restrict__ Q, const float* __restrict__ Km,
    const float* __restrict__ Vm, float* __restrict__ y)
{
    extern __shared__ uint32_t sm[];
    uint32_t* qs  = sm;                     // 128*64
    uint32_t* ksB = qs + 128 * RS_;         // 2 * 64*64
    uint32_t* vsB = ksB + 2 * 64 * RS_;     // 2 * 64*64
    uint32_t* ps  = vsB + 2 * 64 * RS_;     // 128*64

    int tid = threadIdx.x;
    int lane = tid & 31, w = tid >> 5;
    int r = lane >> 2, q4 = lane & 3;
    int qb = blockIdx.x, h = blockIdx.y, b = blockIdx.z;
    int i0 = qb * 128;

    const float* qg = Q + ((size_t)(b * H_ + h) * T_ + i0) * HD_;
    const float* kg = Km + (size_t)(b * H_ + h) * T_ * HD_;
    const float* vg = Vm + (size_t)(b * H_ + h) * T_ * HD_;

    // ---- stage Q (swizzled, pre-scaled by 0.125) ----
#pragma unroll
    for (int l = 0; l < 8; l++) {
        int fi = tid + l * 256;
        int row = fi >> 4, kq = (fi & 15) << 2;
        float4 t4 = *(const float4*)(qg + row * 64 + kq);
        int g = kq >> 4, wrd = (kq >> 2) & 3, sw = swz_(row);
        uint32_t* p = &qs[row * RS_ + wrd];
        p[((((g << 2) | 0) ^ sw) << 2)] = f2tf32(t4.x * 0.125f);
        p[((((g << 2) | 1) ^ sw) << 2)] = f2tf32(t4.y * 0.125f);
        p[((((g << 2) | 2) ^ sw) << 2)] = f2tf32(t4.z * 0.125f);
        p[((((g << 2) | 3) ^ sw) << 2)] = f2tf32(t4.w * 0.125f);
    }

    int nt = 2 * qb + 2;
    float4 kreg[4], vreg[4];
    // prologue: load kv tile 0
#pragma unroll
    for (int l = 0; l < 4; l++) {
        int fi = tid + l * 256;
        int row = fi >> 4, kq = (fi & 15) << 2;
        kreg[l] = *(const float4*)(kg + (size_t)row * 64 + kq);
        vreg[l] = *(const float4*)(vg + (size_t)row * 64 + kq);
    }
    stage_kv(ksB, vsB, kreg, vreg, tid);
    __syncthreads();

    // persistent Q fragments
    int myr = w * 16 + r;
    int sw0 = swz_(myr), sw8 = swz_(myr + 8);
    uint4 aQlo[4], aQhi[4];
#pragma unroll
    for (int g = 0; g < 4; g++) {
        aQlo[g] = *(const uint4*)&qs[myr * RS_ + ((((g << 2) | q4) ^ sw0) << 2)];
        aQhi[g] = *(const uint4*)&qs[(myr + 8) * RS_ + ((((g << 2) | q4) ^ sw8) << 2)];
    }

    float acc[8][4] = {};
    float M0 = -1e30f, M1 = -1e30f, L0 = 0.f, L1 = 0.f;
    int rg0 = i0 + myr, rg1 = rg0 + 8;

    for (int t = 0; t < nt; t++) {
        int cur = t & 1;
        uint32_t* ks = ksB + cur * 64 * RS_;
        uint32_t* vs = vsB + cur * 64 * RS_;

        // prefetch next tile into registers
        if (t + 1 < nt) {
            int j0n = (t + 1) * 64;
#pragma unroll
            for (int l = 0; l < 4; l++) {
                int fi = tid + l * 256;
                int row = fi >> 4, kq = (fi & 15) << 2;
                kreg[l] = *(const float4*)(kg + (size_t)(j0n + row) * 64 + kq);
                vreg[l] = *(const float4*)(vg + (size_t)(j0n + row) * 64 + kq);
            }
        }
        int j0 = t * 64;

        // ---- S = Q K^T (Q pre-scaled) ----
        float s[8][4] = {};
#pragma unroll
        for (int nb = 0; nb < 8; nb++) {
            int krow = nb * 8 + r;
            const uint32_t* kb2 = &ks[krow * RS_];
            int swk = swz_(krow);
#pragma unroll
            for (int g = 0; g < 4; g++) {
                uint4 bb = *(const uint4*)&kb2[(((g << 2) | q4) ^ swk) << 2];
                mma_tf32_k8(s[nb], aQlo[g].x, aQhi[g].x, aQlo[g].y, aQhi[g].y,
                            bb.x, bb.y);
                mma_tf32_k8(s[nb], aQlo[g].z, aQhi[g].z, aQlo[g].w, aQhi[g].w,
                            bb.z, bb.w);
            }
        }

        // ---- mask; row max ----
        float m0 = -1e30f, m1 = -1e30f;
#pragma unroll
        for (int nb = 0; nb < 8; nb++) {
            int c0 = j0 + nb * 8 + q4 * 2;
            bool cm0 = ((c0) % 25) != 24;
            bool cm1 = ((c0 + 1) % 25) != 24;
            s[nb][0] = (cm0 && c0 <= rg0)     ? s[nb][0] : -1e30f;
            s[nb][1] = (cm1 && c0 + 1 <= rg0) ? s[nb][1] : -1e30f;
            s[nb][2] = (cm0 && c0 <= rg1)     ? s[nb][2] : -1e30f;
            s[nb][3] = (cm1 && c0 + 1 <= rg1) ? s[nb][3] : -1e30f;
            m0 = fmaxf(m0, fmaxf(s[nb][0], s[nb][1]));
            m1 = fmaxf(m1, fmaxf(s[nb][2], s[nb][3]));
        }
#pragma unroll
        for (int o = 1; o <= 2; o <<= 1) {
            m0 = fmaxf(m0, __shfl_xor_sync(0xffffffffu, m0, o));
            m1 = fmaxf(m1, __shfl_xor_sync(0xffffffffu, m1, o));
        }

        // ---- online softmax ----
        float Mn0 = fmaxf(M0, m0), Mn1 = fmaxf(M1, m1);
        float al0 = __expf(M0 - Mn0), al1 = __expf(M1 - Mn1);
        M0 = Mn0; M1 = Mn1;
        float rs0 = 0.f, rs1 = 0.f;
#pragma unroll
        for (int nb = 0; nb < 8; nb++) {
            float p0 = __expf(s[nb][0] - Mn0);
            float p1 = __expf(s[nb][1] - Mn0);
            float p2 = __expf(s[nb][2] - Mn1);
            float p3 = __expf(s[nb][3] - Mn1);
            s[nb][0] = p0; s[nb][1] = p1; s[nb][2] = p2; s[nb][3] = p3;
            rs0 += p0 + p1; rs1 += p2 + p3;
        }
#pragma unroll
        for (int o = 1; o <= 2; o <<= 1) {
            rs0 += __shfl_xor_sync(0xffffffffu, rs0, o);
            rs1 += __shfl_xor_sync(0xffffffffu, rs1, o);
        }
        L0 = L0 * al0 + rs0;
        L1 = L1 * al1 + rs1;
#pragma unroll
        for (int db = 0; db < 8; db++) {
            acc[db][0] *= al0; acc[db][1] *= al0;
            acc[db][2] *= al1; acc[db][3] *= al1;
        }

        // ---- stage P (warp-local rows, swizzled) ----
#pragma unroll
        for (int nb = 0; nb < 8; nb++) {
#pragma unroll
            for (int e = 0; e < 2; e++) {
                int kk = nb * 8 + q4 * 2 + e;
                int gq = ((kk >> 4) << 2) | (kk & 3);
                int wd = (kk >> 2) & 3;
                ps[myr * RS_ + (((gq ^ sw0) << 2) + wd)] = f2tf32(s[nb][e]);
                ps[(myr + 8) * RS_ + (((gq ^ sw8) << 2) + wd)] = f2tf32(s[nb][2 + e]);
            }
        }
        __syncwarp();

        // ---- O += P V ----
#pragma unroll
        for (int g = 0; g < 4; g++) {
            uint4 plo = *(const uint4*)&ps[myr * RS_ + ((((g << 2) | q4) ^ sw0) << 2)];
            uint4 phi = *(const uint4*)&ps[(myr + 8) * RS_ + ((((g << 2) | q4) ^ sw8) << 2)];
#pragma unroll
            for (int db = 0; db < 8; db++) {
                int vrow = db * 8 + r;
                uint4 bb = *(const uint4*)&vs[vrow * RS_ + ((((g << 2) | q4) ^ swz_(vrow)) << 2)];
                mma_tf32_k8(acc[db], plo.x, phi.x, plo.y, phi.y, bb.x, bb.y);
                mma_tf32_k8(acc[db], plo.z, phi.z, plo.w, phi.w, bb.z, bb.w);
            }
        }

        // ---- store prefetched tile into the other buffer ----
        if (t + 1 < nt) {
            stage_kv(ksB + (cur ^ 1) * 64 * RS_, vsB + (cur ^ 1) * 64 * RS_,
                     kreg, vreg, tid);
        }
        __syncthreads();
    }

    // ---- epilogue: normalize, write y[B,T,C] ----
    float inv0 = 1.0f / L0, inv1 = 1.0f / L1;
#pragma unroll
    for (int db = 0; db < 8; db++) {
        int c = h * 64 + db * 8 + q4 * 2;
        float2 o0, o1;
        o0.x = acc[db][0] * inv0; o0.y = acc[db][1] * inv0;
        o1.x = acc[db][2] * inv1; o1.y = acc[db][3] * inv1;
        *(float2*)&y[((size_t)(b * T_) + rg0) * C_ + c] = o0;
        *(float2*)&y[((size_t)(b * T_) + rg1) * C_ + c] = o1;
    }
}

// ---------------- launch ----------------
extern "C" void kernel_launch(void* const* d_in, const int* in_sizes, int n_in,
                              void* d_out, int out_size) {
    const float* x  = (const float*)d_in[0];
    const float* Wq = (const float*)d_in[1];
    const float* bq = (const float*)d_in[2];
    const float* Wk = (const float*)d_in[3];
    const float* bk = (const float*)d_in[4];
    const float* Wv = (const float*)d_in[5];
    const float* bv = (const float*)d_in[6];
    const float* Wp = (const float*)d_in[7];
    const float* bp = (const float*)d_in[8];

    float *q, *k, *v, *y;
    cudaGetSymbolAddress((void**)&q, g_q);
    cudaGetSymbolAddress((void**)&k, g_k);
    cudaGetSymbolAddress((void**)&v, g_v);
    cudaGetSymbolAddress((void**)&y, g_y);

    // fused QKV projections (blockIdx.z selects weight set)
    dim3 gqkv(8, 64, 3);
    gemm_tf32<<<gqkv, 256>>>(x, Wq, bq, q, Wk, bk, k, Wv, bv, v, 1);

    const int ATT_SMEM = (128 + 128 + 128 + 128) * RS_ * (int)sizeof(uint32_t); // 131072
    cudaFuncSetAttribute(attn_mma, cudaFuncAttributeMaxDynamicSharedMemorySize, ATT_SMEM);
    attn_mma<<<dim3(T_ / 128, H_, B_), 256, ATT_SMEM>>>(q, k, v, y);

    dim3 gp(8, 64, 1);
    gemm_tf32<<<gp, 256>>>(y, Wp, bp, (float*)d_out,
                           Wp, bp, (float*)d_out, Wp, bp, (float*)d_out, 0);
}

// round 14
// speedup vs baseline: 3.2687x; 1.1543x over previous
#include <cuda_runtime.h>
#include <cuda_bf16.h>
#include <cstdint>

#define B_ 4
#define T_ 2048
#define C_ 1024
#define H_ 16
#define HD_ 64

// ---------------- scratch (allocation-free: __device__ globals) ----------------
// all tf32-bit u32, pre-permuted layouts
__device__ uint32_t g_xp[8192*1024];      // 32 MB  x, gemm-A perm
__device__ uint32_t g_wq[1024*1024];      // 4 MB   weights, gemm-B perm
__device__ uint32_t g_wk[1024*1024];
__device__ uint32_t g_wv[1024*1024];
__device__ uint32_t g_wp[1024*1024];
__device__ uint32_t g_q[B_*H_*T_*HD_];    // 32 MB  attn-q swizzled (pre-scaled 1/8)
__device__ uint32_t g_k[B_*H_*T_*HD_];    // 32 MB  attn-k swizzled
__device__ uint32_t g_v[B_*H_*T_*HD_];    // 32 MB  attn-v swizzled TRANSPOSED [d][key]
__device__ uint32_t g_y[8192*1024];       // 32 MB  y, gemm-A perm

// ---------------- helpers ----------------
__device__ __forceinline__ uint32_t f2tf32(float x) {
    uint32_t r;
    asm("cvt.rna.tf32.f32 %0, %1;" : "=r"(r) : "f"(x));
    return r;
}

__device__ __forceinline__ void mma_tf32_k8(
    float* c, uint32_t a0, uint32_t a1, uint32_t a2, uint32_t a3,
    uint32_t b0, uint32_t b1)
{
    asm volatile(
        "mma.sync.aligned.m16n8k8.row.col.f32.tf32.tf32.f32 "
        "{%0,%1,%2,%3}, {%4,%5,%6,%7}, {%8,%9}, {%0,%1,%2,%3};"
        : "+f"(c[0]), "+f"(c[1]), "+f"(c[2]), "+f"(c[3])
        : "r"(a0), "r"(a1), "r"(a2), "r"(a3), "r"(b0), "r"(b1));
}

__device__ __forceinline__ void cpa16(uint32_t dst_smem, const void* src) {
    asm volatile("cp.async.cg.shared.global [%0], [%1], 16;"
                 :: "r"(dst_smem), "l"(src));
}
#define CP_COMMIT() asm volatile("cp.async.commit_group;")
#define CP_WAIT0()  asm volatile("cp.async.wait_group 0;")

// attn swizzle (stride-64 rows, 16 granules of 4 words); uses row bits 0..4 only
__device__ __forceinline__ int swz_(int row) {
    return ((((row) ^ ((row) >> 2)) & 1) << 2)
         | ((((row) >> 3) & 1) << 1)
         | (((row) >> 4) & 1);
}
#define RS_ 64

// GEMM swizzle (stride-16 rows, 4 granules of 4 words)
__device__ __forceinline__ int gsw_(int row) { return (row >> 1) & 3; }

// ---------------- prep: f32 [rows][1024] -> tf32 gemm-perm u32 ----------------
// word (r, kc*16 + ((j^gsw_(r))<<2) + w) = tf32(in[r][kc*16 + w*4 + j])
__global__ void perm_tf32(const float* __restrict__ in, uint32_t* __restrict__ out,
                          int total /* rows*64 */) {
    int idx = blockIdx.x * 256 + threadIdx.x;
    if (idx >= total) return;
    int r = idx >> 6, kc = idx & 63;
    float4 f[4];
    const float4* src = (const float4*)(in + (size_t)r * 1024 + kc * 16);
#pragma unroll
    for (int w = 0; w < 4; w++) f[w] = src[w];
    const float* fp = (const float*)f;     // fp[w*4 + j]
    int sg = gsw_(r);
    uint4* dst = (uint4*)(out + (size_t)r * 1024 + kc * 16);
#pragma unroll
    for (int g = 0; g < 4; g++) {
        int j = g ^ sg;
        uint4 o;
        o.x = f2tf32(fp[0 * 4 + j]);
        o.y = f2tf32(fp[1 * 4 + j]);
        o.z = f2tf32(fp[2 * 4 + j]);
        o.w = f2tf32(fp[3 * 4 + j]);
        dst[g] = o;
    }
}

// ---------------- tf32 GEMM: out = A @ W^T + bias ----------------
// A, W pre-permuted tf32; staging = pure cp.async. QKV fused via blockIdx.z.
// headed: z==0 -> q (attn layout, scale 1/8), z==1 -> k (attn layout),
//         z==2 -> v (attn TRANSPOSED layout). !headed: plain f32 [M,1024].
__global__ __launch_bounds__(256) void gemm_tf32(
    const uint32_t* __restrict__ A,
    const uint32_t* __restrict__ W0, const float* __restrict__ b0, void* o0,
    const uint32_t* __restrict__ W1, const float* __restrict__ b1, void* o1,
    const uint32_t* __restrict__ W2, const float* __restrict__ b2, void* o2,
    int headed)
{
    int z = blockIdx.z;
    const uint32_t* W = W0; const float* bias = b0; void* outp = o0;
    if (z == 1) { W = W1; bias = b1; outp = o1; }
    else if (z == 2) { W = W2; bias = b2; outp = o2; }
    float scale = (headed && z == 0) ? 0.125f : 1.0f;
    bool vmode = (headed && z == 2);

    const int K = 1024;
    __shared__ uint32_t As[2][128 * 16];
    __shared__ uint32_t Bs[2][128 * 16];
    uint32_t sA = (uint32_t)__cvta_generic_to_shared(&As[0][0]);
    uint32_t sB = (uint32_t)__cvta_generic_to_shared(&Bs[0][0]);

    int tid = threadIdx.x;
    int lane = tid & 31, warp = tid >> 5;
    int wm = warp & 1, wn = warp >> 1;     // 2 (M) x 4 (N)
    int m0 = blockIdx.y * 128, n0 = blockIdx.x * 128;
    int r = lane >> 2, q = lane & 3;
    int sfr = gsw_(r);

    // granule copy coords (gi = tid + l*256; row = gi>>2, g = gi&3)
    int grow[2], gg[2];
#pragma unroll
    for (int l = 0; l < 2; l++) { int gi = tid + l * 256; grow[l] = gi >> 2; gg[l] = gi & 3; }

    float acc[16][4] = {};

    // prologue: stage k0=0 into buf 0
#pragma unroll
    for (int l = 0; l < 2; l++) {
        cpa16(sA + (grow[l] * 16 + gg[l] * 4) * 4,
              A + (size_t)(m0 + grow[l]) * 1024 + gg[l] * 4);
        cpa16(sB + (grow[l] * 16 + gg[l] * 4) * 4,
              W + (size_t)(n0 + grow[l]) * 1024 + gg[l] * 4);
    }
    CP_COMMIT();

    for (int k0 = 0; k0 < K; k0 += 16) {
        int cur = (k0 >> 4) & 1;
        CP_WAIT0();
        __syncthreads();
        if (k0 + 16 < K) {
            int nb = (cur ^ 1) * 2048;
#pragma unroll
            for (int l = 0; l < 2; l++) {
                cpa16(sA + (nb + grow[l] * 16 + gg[l] * 4) * 4,
                      A + (size_t)(m0 + grow[l]) * 1024 + k0 + 16 + gg[l] * 4);
                cpa16(sB + (nb + grow[l] * 16 + gg[l] * 4) * 4,
                      W + (size_t)(n0 + grow[l]) * 1024 + k0 + 16 + gg[l] * 4);
            }
            CP_COMMIT();
        }

        uint4 aLo[4], aHi[4], bV[4];
#pragma unroll
        for (int mt = 0; mt < 4; mt++) {
            int row = wm * 64 + mt * 16 + r;
            aLo[mt] = *(const uint4*)&As[cur][row * 16 + ((q ^ sfr) << 2)];
            aHi[mt] = *(const uint4*)&As[cur][(row + 8) * 16 + ((q ^ sfr) << 2)];
        }
#pragma unroll
        for (int nt = 0; nt < 4; nt++) {
            int col = wn * 32 + nt * 8 + r;
            bV[nt] = *(const uint4*)&Bs[cur][col * 16 + ((q ^ sfr) << 2)];
        }

#pragma unroll
        for (int mt = 0; mt < 4; mt++)
#pragma unroll
            for (int nt = 0; nt < 4; nt++) {
                float* c = acc[mt * 4 + nt];
                mma_tf32_k8(c, aLo[mt].x, aHi[mt].x, aLo[mt].y, aHi[mt].y,
                            bV[nt].x, bV[nt].y);
                mma_tf32_k8(c, aLo[mt].z, aHi[mt].z, aLo[mt].w, aHi[mt].w,
                            bV[nt].z, bV[nt].w);
            }
    }

    // ---- epilogue ----
#pragma unroll
    for (int mt = 0; mt < 4; mt++) {
        int rowb = m0 + wm * 64 + mt * 16 + r;
#pragma unroll
        for (int nt = 0; nt < 4; nt++) {
            int colb = n0 + wn * 32 + nt * 8 + q * 2;
            float bb0 = bias[colb], bb1 = bias[colb + 1];
            float* c = acc[mt * 4 + nt];
#pragma unroll
            for (int hh = 0; hh < 2; hh++) {
                int m = rowb + hh * 8;
                float v0 = c[hh * 2 + 0] + bb0;
                float v1 = c[hh * 2 + 1] + bb1;
                if (!headed) {
                    float2 o; o.x = v0; o.y = v1;
                    *(float2*)&((float*)outp)[(size_t)m * 1024 + colb] = o;
                } else {
                    uint32_t* out = (uint32_t*)outp;
                    int b = m >> 11, t = m & 2047;
                    int h = colb >> 6, d = colb & 63;
                    if (vmode) {
                        // v transposed: [b,h][ktile][d][64 key-words]
                        size_t base = ((size_t)((b << 4) + h) * 32 + (t >> 6)) * 64;
                        int kr = t & 63;
                        int gk = ((kr >> 4) << 2) | (kr & 3), wk = (kr >> 2) & 3;
                        out[(base + d) * 64 + ((gk ^ swz_(d)) << 2) + wk]           = f2tf32(v0);
                        out[(base + d + 1) * 64 + ((gk ^ swz_(d + 1)) << 2) + wk]   = f2tf32(v1);
                    } else {
                        // q/k: [b,h][token][64 d-words], swz by token
                        size_t base = ((size_t)((b << 4) + h) * 2048 + t) * 64;
                        int sw = swz_(t);
                        int g0 = ((d >> 4) << 2) | (d & 3);
                        int g1 = (((d + 1) >> 4) << 2) | ((d + 1) & 3);
                        out[base + ((g0 ^ sw) << 2) + ((d >> 2) & 3)] = f2tf32(v0 * scale);
                        out[base + ((g1 ^ sw) << 2) + ((d >> 2) & 3)] = f2tf32(v1 * scale);
                    }
                }
            }
        }
    }
}

// ---------------- tensor-core flash attention with RL mask ----------------
// mask: allowed iff (col <= row) && (col % 25 != 24)
// q/k/v pre-converted + pre-swizzled in global: staging = pure cp.async.
// CTA: 128 q-rows of one (b,h); 8 warps x 16 rows; kv tiles of 64; double-buffered.
__global__ __launch_bounds__(256) void attn_mma(
    const uint32_t* __restrict__ Q, const uint32_t* __restrict__ Km,
    const uint32_t* __restrict__ Vm, uint32_t* __restrict__ y)
{
    extern __shared__ uint32_t sm[];
    uint32_t* qs  = sm;                     // 128*64
    uint32_t* ksB = qs + 128 * RS_;         // 2 * 64*64
    uint32_t* vsB = ksB + 2 * 64 * RS_;     // 2 * 64*64
    uint32_t* ps  = vsB + 2 * 64 * RS_;     // 128*64
    uint32_t sQ = (uint32_t)__cvta_generic_to_shared(qs);
    uint32_t sK = (uint32_t)__cvta_generic_to_shared(ksB);
    uint32_t sV = (uint32_t)__cvta_generic_to_shared(vsB);

    int tid = threadIdx.x;
    int lane = tid & 31, w = tid >> 5;
    int r = lane >> 2, q4 = lane & 3;
    int qb = (gridDim.x - 1) - blockIdx.x;  // longest CTAs first
    int h = blockIdx.y, b = blockIdx.z;
    int i0 = qb * 128;

    const uint32_t* qg = Q + ((size_t)(b * H_ + h) * T_ + i0) * HD_;
    const uint32_t* kg = Km + (size_t)(b * H_ + h) * T_ * HD_;
    const uint32_t* vg = Vm + (size_t)(b * H_ + h) * T_ * HD_;  // [ktile][d][64]

    int nt = 2 * qb + 2;

    // prologue: Q tile (2048 granules) + KV tile 0 (1024 + 1024)
#pragma unroll
    for (int l = 0; l < 8; l++) {
        int gi = tid + l * 256;
        int row = gi >> 4, g = gi & 15;
        cpa16(sQ + (row * RS_ + g * 4) * 4, qg + (size_t)row * 64 + g * 4);
    }
#pragma unroll
    for (int l = 0; l < 4; l++) {
        int gi = tid + l * 256;
        int row = gi >> 4, g = gi & 15;
        cpa16(sK + (row * RS_ + g * 4) * 4, kg + (size_t)row * 64 + g * 4);
        cpa16(sV + (row * RS_ + g * 4) * 4, vg + (size_t)row * 64 + g * 4);
    }
    CP_COMMIT();

    uint4 aQlo[4], aQhi[4];
    int myr = w * 16 + r;
    int sw0 = swz_(myr), sw8 = swz_(myr + 8);

    float acc[8][4] = {};
    float M0 = -1e30f, M1 = -1e30f, L0 = 0.f, L1 = 0.f;
    int rg0 = i0 + myr, rg1 = rg0 + 8;

    for (int t = 0; t < nt; t++) {
        int cur = t & 1;
        uint32_t* ks = ksB + cur * 64 * RS_;
        uint32_t* vs = vsB + cur * 64 * RS_;

        CP_WAIT0();
        __syncthreads();

        // prefetch next KV tile into other buffer (safe: all warps past prev tile)
        if (t + 1 < nt) {
            int nb = (cur ^ 1) * 64 * RS_;
            size_t j0n = (size_t)(t + 1) * 64;
#pragma unroll
            for (int l = 0; l < 4; l++) {
                int gi = tid + l * 256;
                int row = gi >> 4, g = gi & 15;
                cpa16(sK + (nb + row * RS_ + g * 4) * 4, kg + (j0n + row) * 64 + g * 4);
                cpa16(sV + (nb + row * RS_ + g * 4) * 4, vg + (j0n + row) * 64 + g * 4);
            }
            CP_COMMIT();
        }

        if (t == 0) {
            // persistent Q fragments
#pragma unroll
            for (int g = 0; g < 4; g++) {
                aQlo[g] = *(const uint4*)&qs[myr * RS_ + ((((g << 2) | q4) ^ sw0) << 2)];
                aQhi[g] = *(const uint4*)&qs[(myr + 8) * RS_ + ((((g << 2) | q4) ^ sw8) << 2)];
            }
        }
        int j0 = t * 64;

        // ---- S = Q K^T (Q pre-scaled) ----
        float s[8][4] = {};
#pragma unroll
        for (int nb2 = 0; nb2 < 8; nb2++) {
            int krow = nb2 * 8 + r;
            const uint32_t* kb2 = &ks[krow * RS_];
            int swk = swz_(krow);
#pragma unroll
            for (int g = 0; g < 4; g++) {
                uint4 bb = *(const uint4*)&kb2[(((g << 2) | q4) ^ swk) << 2];
                mma_tf32_k8(s[nb2], aQlo[g].x, aQhi[g].x, aQlo[g].y, aQhi[g].y,
                            bb.x, bb.y);
                mma_tf32_k8(s[nb2], aQlo[g].z, aQhi[g].z, aQlo[g].w, aQhi[g].w,
                            bb.z, bb.w);
            }
        }

        // ---- mask; row max ----
        float m0 = -1e30f, m1 = -1e30f;
#pragma unroll
        for (int nb2 = 0; nb2 < 8; nb2++) {
            int c0 = j0 + nb2 * 8 + q4 * 2;
            bool cm0 = ((c0) % 25) != 24;
            bool cm1 = ((c0 + 1) % 25) != 24;
            s[nb2][0] = (cm0 && c0 <= rg0)     ? s[nb2][0] : -1e30f;
            s[nb2][1] = (cm1 && c0 + 1 <= rg0) ? s[nb2][1] : -1e30f;
            s[nb2][2] = (cm0 && c0 <= rg1)     ? s[nb2][2] : -1e30f;
            s[nb2][3] = (cm1 && c0 + 1 <= rg1) ? s[nb2][3] : -1e30f;
            m0 = fmaxf(m0, fmaxf(s[nb2][0], s[nb2][1]));
            m1 = fmaxf(m1, fmaxf(s[nb2][2], s[nb2][3]));
        }
#pragma unroll
        for (int o = 1; o <= 2; o <<= 1) {
            m0 = fmaxf(m0, __shfl_xor_sync(0xffffffffu, m0, o));
            m1 = fmaxf(m1, __shfl_xor_sync(0xffffffffu, m1, o));
        }

        // ---- online softmax ----
        float Mn0 = fmaxf(M0, m0), Mn1 = fmaxf(M1, m1);
        float al0 = __expf(M0 - Mn0), al1 = __expf(M1 - Mn1);
        M0 = Mn0; M1 = Mn1;
        float rs0 = 0.f, rs1 = 0.f;
#pragma unroll
        for (int nb2 = 0; nb2 < 8; nb2++) {
            float p0 = __expf(s[nb2][0] - Mn0);
            float p1 = __expf(s[nb2][1] - Mn0);
            float p2 = __expf(s[nb2][2] - Mn1);
            float p3 = __expf(s[nb2][3] - Mn1);
            s[nb2][0] = p0; s[nb2][1] = p1; s[nb2][2] = p2; s[nb2][3] = p3;
            rs0 += p0 + p1; rs1 += p2 + p3;
        }
#pragma unroll
        for (int o = 1; o <= 2; o <<= 1) {
            rs0 += __shfl_xor_sync(0xffffffffu, rs0, o);
            rs1 += __shfl_xor_sync(0xffffffffu, rs1, o);
        }
        L0 = L0 * al0 + rs0;
        L1 = L1 * al1 + rs1;
#pragma unroll
        for (int db = 0; db < 8; db++) {
            acc[db][0] *= al0; acc[db][1] *= al0;
            acc[db][2] *= al1; acc[db][3] *= al1;
        }

        // ---- stage P (warp-local rows, swizzled) ----
#pragma unroll
        for (int nb2 = 0; nb2 < 8; nb2++) {
#pragma unroll
            for (int e = 0; e < 2; e++) {
                int kk = nb2 * 8 + q4 * 2 + e;
                int gq = ((kk >> 4) << 2) | (kk & 3);
                int wd = (kk >> 2) & 3;
                ps[myr * RS_ + (((gq ^ sw0) << 2) + wd)] = f2tf32(s[nb2][e]);
                ps[(myr + 8) * RS_ + (((gq ^ sw8) << 2) + wd)] = f2tf32(s[nb2][2 + e]);
            }
        }
        __syncwarp();

        // ---- O += P V ----
#pragma unroll
        for (int g = 0; g < 4; g++) {
            uint4 plo = *(const uint4*)&ps[myr * RS_ + ((((g << 2) | q4) ^ sw0) << 2)];
            uint4 phi = *(const uint4*)&ps[(myr + 8) * RS_ + ((((g << 2) | q4) ^ sw8) << 2)];
#pragma unroll
            for (int db = 0; db < 8; db++) {
                int vrow = db * 8 + r;
                uint4 bb = *(const uint4*)&vs[vrow * RS_ + ((((g << 2) | q4) ^ swz_(vrow)) << 2)];
                mma_tf32_k8(acc[db], plo.x, phi.x, plo.y, phi.y, bb.x, bb.y);
                mma_tf32_k8(acc[db], plo.z, phi.z, plo.w, phi.w, bb.z, bb.w);
            }
        }
    }

    // ---- epilogue: normalize, write y in gemm-A perm tf32 layout ----
    float inv0 = 1.0f / L0, inv1 = 1.0f / L1;
    size_t mr0 = ((size_t)b * 2048 + rg0) * 1024;
    size_t mr1 = ((size_t)b * 2048 + rg1) * 1024;
    int sg0 = (rg0 >> 1) & 3, sg1 = (rg1 >> 1) & 3;   // == (m>>1)&3 since b*2048 ≡ 0 mod 8
#pragma unroll
    for (int db = 0; db < 8; db++) {
        int c = h * 64 + db * 8 + q4 * 2;
        int kc16 = (c >> 4) << 4, wd = (c >> 2) & 3, j = c & 3;
        y[mr0 + kc16 + (((j ^ sg0) & 3) << 2) + wd]       = f2tf32(acc[db][0] * inv0);
        y[mr0 + kc16 + ((((j + 1) ^ sg0) & 3) << 2) + wd] = f2tf32(acc[db][1] * inv0);
        y[mr1 + kc16 + (((j ^ sg1) & 3) << 2) + wd]       = f2tf32(acc[db][2] * inv1);
        y[mr1 + kc16 + ((((j + 1) ^ sg1) & 3) << 2) + wd] = f2tf32(acc[db][3] * inv1);
    }
}

// ---------------- launch ----------------
extern "C" void kernel_launch(void* const* d_in, const int* in_sizes, int n_in,
                              void* d_out, int out_size) {
    const float* x  = (const float*)d_in[0];
    const float* Wq = (const float*)d_in[1];
    const float* bq = (const float*)d_in[2];
    const float* Wk = (const float*)d_in[3];
    const float* bk = (const float*)d_in[4];
    const float* Wv = (const float*)d_in[5];
    const float* bv = (const float*)d_in[6];
    const float* Wp = (const float*)d_in[7];
    const float* bp = (const float*)d_in[8];

    uint32_t *xp, *wq, *wk, *wv, *wp, *q, *k, *v, *y;
    cudaGetSymbolAddress((void**)&xp, g_xp);
    cudaGetSymbolAddress((void**)&wq, g_wq);
    cudaGetSymbolAddress((void**)&wk, g_wk);
    cudaGetSymbolAddress((void**)&wv, g_wv);
    cudaGetSymbolAddress((void**)&wp, g_wp);
    cudaGetSymbolAddress((void**)&q, g_q);
    cudaGetSymbolAddress((void**)&k, g_k);
    cudaGetSymbolAddress((void**)&v, g_v);
    cudaGetSymbolAddress((void**)&y, g_y);

    // one-time converts into gemm-perm tf32
    perm_tf32<<<2048, 256>>>(x, xp, 8192 * 64);
    perm_tf32<<<256, 256>>>(Wq, wq, 1024 * 64);
    perm_tf32<<<256, 256>>>(Wk, wk, 1024 * 64);
    perm_tf32<<<256, 256>>>(Wv, wv, 1024 * 64);
    perm_tf32<<<256, 256>>>(Wp, wp, 1024 * 64);

    // fused QKV projections -> attn layouts
    dim3 gqkv(8, 64, 3);
    gemm_tf32<<<gqkv, 256>>>(xp, wq, bq, q, wk, bk, k, wv, bv, v, 1);

    const int ATT_SMEM = (128 + 128 + 128 + 128) * RS_ * (int)sizeof(uint32_t); // 131072
    cudaFuncSetAttribute(attn_mma, cudaFuncAttributeMaxDynamicSharedMemorySize, ATT_SMEM);
    attn_mma<<<dim3(T_ / 128, H_, B_), 256, ATT_SMEM>>>(q, k, v, y);

    // output projection (plain f32 out)
    dim3 gp(8, 64, 1);
    gemm_tf32<<<gp, 256>>>(y, wp, bp, d_out, wp, bp, d_out, wp, bp, d_out, 0);
}